// round 2
// baseline (speedup 1.0000x reference)
#include <cuda_runtime.h>
#include <cuda_bf16.h>

// Problem constants (fixed by setup_inputs)
#define NN    200000
#define D_IN  128
#define HID   256
#define OUTD  128
#define BATCH 2048
#define KF    16
#define N2    (BATCH*KF + BATCH)   // 34816
#define E1    (BATCH*KF)           // 32768

// Scratch (device globals; no runtime allocation allowed)
__device__ float g_Acat[N2 * 2 * D_IN];     // [N2, 256] = [agg2 | hn1]
__device__ float g_h1[N2 * HID];            // [N2, 256]
__device__ float g_Bcat[BATCH * 2 * HID];   // [2048, 512] = [agg1 | hn2]
__device__ float g_W1[HID * 2 * D_IN];      // [256, 256] = [W1n | W1h]
__device__ float g_b1[HID];
__device__ float g_W2[OUTD * 2 * HID];      // [128, 512] = [W2n | W2h]
__device__ float g_b2[OUTD];

// ---------------------------------------------------------------------------
// Weight prep: concat weights along input dim, sum biases
// ---------------------------------------------------------------------------
__global__ void prep_w1(const float* __restrict__ W1n, const float* __restrict__ b1n,
                        const float* __restrict__ W1h, const float* __restrict__ b1h) {
    int h = blockIdx.x;          // 0..255
    int k = threadIdx.x;         // 0..255
    g_W1[h * 256 + k] = (k < D_IN) ? W1n[h * D_IN + k] : W1h[h * D_IN + (k - D_IN)];
    if (k == 0) g_b1[h] = b1n[h] + b1h[h];
}

__global__ void prep_w2(const float* __restrict__ W2n, const float* __restrict__ b2n,
                        const float* __restrict__ W2h, const float* __restrict__ b2h) {
    int n = blockIdx.x;          // 0..127
    int k = threadIdx.x;         // 0..511
    g_W2[n * 512 + k] = (k < HID) ? W2n[n * HID + k] : W2h[n * HID + (k - HID)];
    if (k == 0) g_b2[n] = b2n[n] + b2h[n];
}

// ---------------------------------------------------------------------------
// Kernel 1: build Acat[i] = [ sum_j x[nbr2[i*16+j]] | x[nodes2[i]] * decay(i) ]
// 128 threads per row (one per feature dim)
// ---------------------------------------------------------------------------
__global__ void build_acat(const float* __restrict__ x,
                           const int*   __restrict__ nodes2,
                           const int*   __restrict__ nbr2,
                           const float* __restrict__ t2,
                           const float* __restrict__ n_times2,
                           const float* __restrict__ t_kernel) {
    const int i = blockIdx.x;     // row 0..N2-1
    const int d = threadIdx.x;    // 0..127
    const float tk = t_kernel[0];

    const int* nb = nbr2 + (long)i * KF;
    float s = 0.f;
#pragma unroll
    for (int j = 0; j < KF; ++j) {
        s += x[(long)nb[j] * D_IN + d];
    }
    g_Acat[(long)i * 256 + d] = s;

    float dec = __expf(-tk * (t2[i] - n_times2[i]));
    g_Acat[(long)i * 256 + 128 + d] = x[(long)nodes2[i] * D_IN + d] * dec;
}

// ---------------------------------------------------------------------------
// Kernel 2: SGEMM-NT + bias + relu.  C[M,N] = relu(A[M,K] * W[N,K]^T + bias)
// BM=BN=128, BK=16, 256 threads, 8x8 per thread in 4+4 split layout
// ---------------------------------------------------------------------------
__global__ __launch_bounds__(256) void gemm1_relu(const float* __restrict__ A,
                                                  const float* __restrict__ W,
                                                  const float* __restrict__ bias,
                                                  float* __restrict__ C,
                                                  int M, int N, int K) {
    const int BM = 128, BN = 128, BK = 16;
    __shared__ float As[BK][BM];
    __shared__ float Ws[BK][BN];

    const int bn = blockIdx.x * BN;
    const int bm = blockIdx.y * BM;
    const int tid = threadIdx.x;
    const int tx = tid & 15;
    const int ty = tid >> 4;

    float acc[8][8];
#pragma unroll
    for (int i = 0; i < 8; ++i)
#pragma unroll
        for (int j = 0; j < 8; ++j) acc[i][j] = 0.f;

    for (int k0 = 0; k0 < K; k0 += BK) {
        // load A tile: 128x16 = 512 float4s / 256 threads = 2 each
#pragma unroll
        for (int p = 0; p < 2; ++p) {
            int idx = tid + p * 256;        // 0..511
            int r = idx >> 2;               // 0..127
            int c4 = idx & 3;               // 0..3
            float4 v = *(const float4*)&A[(long)(bm + r) * K + k0 + c4 * 4];
            As[c4 * 4 + 0][r] = v.x; As[c4 * 4 + 1][r] = v.y;
            As[c4 * 4 + 2][r] = v.z; As[c4 * 4 + 3][r] = v.w;
        }
#pragma unroll
        for (int p = 0; p < 2; ++p) {
            int idx = tid + p * 256;
            int r = idx >> 2;
            int c4 = idx & 3;
            float4 v = *(const float4*)&W[(long)(bn + r) * K + k0 + c4 * 4];
            Ws[c4 * 4 + 0][r] = v.x; Ws[c4 * 4 + 1][r] = v.y;
            Ws[c4 * 4 + 2][r] = v.z; Ws[c4 * 4 + 3][r] = v.w;
        }
        __syncthreads();

#pragma unroll
        for (int kk = 0; kk < BK; ++kk) {
            float4 a0 = *(const float4*)&As[kk][ty * 4];
            float4 a1 = *(const float4*)&As[kk][64 + ty * 4];
            float4 b0 = *(const float4*)&Ws[kk][tx * 4];
            float4 b1 = *(const float4*)&Ws[kk][64 + tx * 4];
            float a[8] = {a0.x, a0.y, a0.z, a0.w, a1.x, a1.y, a1.z, a1.w};
            float b[8] = {b0.x, b0.y, b0.z, b0.w, b1.x, b1.y, b1.z, b1.w};
#pragma unroll
            for (int i = 0; i < 8; ++i)
#pragma unroll
                for (int j = 0; j < 8; ++j) acc[i][j] += a[i] * b[j];
        }
        __syncthreads();
    }

    // epilogue: rows {bm+ty*4+i, bm+64+ty*4+i}, cols {bn+tx*4+j, bn+64+tx*4+j}
#pragma unroll
    for (int ih = 0; ih < 2; ++ih) {
#pragma unroll
        for (int i = 0; i < 4; ++i) {
            int row = bm + ih * 64 + ty * 4 + i;
#pragma unroll
            for (int jh = 0; jh < 2; ++jh) {
                int col = bn + jh * 64 + tx * 4;
                float4 v;
                float* accp = &acc[ih * 4 + i][jh * 4];
                v.x = accp[0] + bias[col + 0];
                v.y = accp[1] + bias[col + 1];
                v.z = accp[2] + bias[col + 2];
                v.w = accp[3] + bias[col + 3];
                v.x = v.x > 0.f ? v.x : 0.f;
                v.y = v.y > 0.f ? v.y : 0.f;
                v.z = v.z > 0.f ? v.z : 0.f;
                v.w = v.w > 0.f ? v.w : 0.f;
                *(float4*)&C[(long)row * N + col] = v;
            }
        }
    }
}

// ---------------------------------------------------------------------------
// Kernel 3: build Bcat[b] = [ sum_j h1[b*16+j] | h1[E1+b] * decay2(b) ]
// 256 threads per row (one per hid dim)
// ---------------------------------------------------------------------------
__global__ void build_bcat(const float* __restrict__ ts,
                           const float* __restrict__ n_times1,
                           const float* __restrict__ t_kernel) {
    const int b = blockIdx.x;     // 0..2047
    const int d = threadIdx.x;    // 0..255
    const float tk = t_kernel[0];

    float s = 0.f;
#pragma unroll
    for (int j = 0; j < KF; ++j) {
        s += g_h1[(long)(b * KF + j) * HID + d];
    }
    g_Bcat[(long)b * 512 + d] = s;

    float dec = __expf(-tk * (ts[b] - n_times1[b]));
    g_Bcat[(long)b * 512 + 256 + d] = g_h1[(long)(E1 + b) * HID + d] * dec;
}

// ---------------------------------------------------------------------------
// Kernel 4: small GEMM  out[2048,128] = relu(Bcat[2048,512] @ W2[128,512]^T + b2)
// BM=16 rows per block, full N=128, chunked K (BKW=32). 256 threads.
// ---------------------------------------------------------------------------
__global__ __launch_bounds__(256) void gemm2_relu(float* __restrict__ out) {
    __shared__ float As[16][512];     // 32 KB
    __shared__ float Ws[32][128];     // 16 KB
    const int bm = blockIdx.x * 16;
    const int tid = threadIdx.x;

    // load A rows (16x512 = 2048 float4 / 256 threads = 8 each)
#pragma unroll
    for (int p = 0; p < 8; ++p) {
        int idx = tid + p * 256;      // float4 index 0..2047
        int r = idx >> 7;             // 0..15
        int c = idx & 127;            // 0..127 (float4 within row)
        *(float4*)&As[r][c * 4] = *(const float4*)&g_Bcat[(long)(bm + r) * 512 + c * 4];
    }
    __syncthreads();

    const int tx = tid & 127;         // output col
    const int ty = tid >> 7;          // 0..1 -> rows ty*8..ty*8+7
    float acc[8];
#pragma unroll
    for (int i = 0; i < 8; ++i) acc[i] = 0.f;

    for (int ch = 0; ch < 16; ++ch) {
        // load Ws[32][128]: Ws[k][n] = W2[n*512 + ch*32 + k]; 1024 float4 / 256 = 4 each
#pragma unroll
        for (int p = 0; p < 4; ++p) {
            int idx = tid + p * 256;  // 0..1023
            int n = idx >> 3;         // 0..127
            int k4 = idx & 7;         // 0..7
            float4 v = *(const float4*)&g_W2[(long)n * 512 + ch * 32 + k4 * 4];
            Ws[k4 * 4 + 0][n] = v.x; Ws[k4 * 4 + 1][n] = v.y;
            Ws[k4 * 4 + 2][n] = v.z; Ws[k4 * 4 + 3][n] = v.w;
        }
        __syncthreads();
#pragma unroll
        for (int k = 0; k < 32; ++k) {
            float bv = Ws[k][tx];
#pragma unroll
            for (int i = 0; i < 8; ++i)
                acc[i] += As[ty * 8 + i][ch * 32 + k] * bv;
        }
        __syncthreads();
    }

    float bb = g_b2[tx];
#pragma unroll
    for (int i = 0; i < 8; ++i) {
        float v = acc[i] + bb;
        out[(long)(bm + ty * 8 + i) * OUTD + tx] = v > 0.f ? v : 0.f;
    }
}

// ---------------------------------------------------------------------------
// Launch
// ---------------------------------------------------------------------------
extern "C" void kernel_launch(void* const* d_in, const int* in_sizes, int n_in,
                              void* d_out, int out_size) {
    const float* x        = (const float*)d_in[0];
    const float* ts       = (const float*)d_in[1];
    const float* t2       = (const float*)d_in[2];
    const float* n_times1 = (const float*)d_in[3];
    const float* n_times2 = (const float*)d_in[4];
    const float* W1n      = (const float*)d_in[5];
    const float* b1n      = (const float*)d_in[6];
    const float* W1h      = (const float*)d_in[7];
    const float* b1h      = (const float*)d_in[8];
    const float* W2n      = (const float*)d_in[9];
    const float* b2n      = (const float*)d_in[10];
    const float* W2h      = (const float*)d_in[11];
    const float* b2h      = (const float*)d_in[12];
    const float* t_kernel = (const float*)d_in[13];
    const int*   nodes2   = (const int*)d_in[14];
    const int*   nbr2     = (const int*)d_in[15];
    // d_in[16] = seg2, d_in[17] = seg1 -- contiguous repeat(arange,K); not needed
    float* out = (float*)d_out;

    float *pAcat, *pW1, *pb1, *ph1;
    cudaGetSymbolAddress((void**)&pAcat, g_Acat);
    cudaGetSymbolAddress((void**)&pW1, g_W1);
    cudaGetSymbolAddress((void**)&pb1, g_b1);
    cudaGetSymbolAddress((void**)&ph1, g_h1);

    prep_w1<<<HID, 256>>>(W1n, b1n, W1h, b1h);
    prep_w2<<<OUTD, 512>>>(W2n, b2n, W2h, b2h);

    build_acat<<<N2, 128>>>(x, nodes2, nbr2, t2, n_times2, t_kernel);

    dim3 g1(256 / 128, N2 / 128);   // (2, 272)
    gemm1_relu<<<g1, 256>>>(pAcat, pW1, pb1, ph1, N2, 256, 256);

    build_bcat<<<BATCH, 256>>>(ts, n_times1, t_kernel);

    gemm2_relu<<<BATCH / 16, 256>>>(out);
}

// round 5
// speedup vs baseline: 1.5069x; 1.5069x over previous
#include <cuda_runtime.h>
#include <cuda_bf16.h>
#include <cstdint>

// Problem constants (fixed by setup_inputs)
#define NN    200000
#define D_IN  128
#define HID   256
#define OUTD  128
#define BATCH 2048
#define KF    16
#define N2    (BATCH*KF + BATCH)   // 34816
#define E1    (BATCH*KF)           // 32768

// Scratch (device globals; no runtime allocation allowed)
__device__ float g_Acat[N2 * 2 * D_IN];     // [N2, 256] = [agg2 | hn1]
__device__ float g_h1[N2 * HID];            // [N2, 256]
__device__ float g_Bcat[BATCH * 2 * HID];   // [2048, 512] = [agg1 | hn2]
__device__ float g_W1[HID * 2 * D_IN];      // [256, 256] = [W1n | W1h]
__device__ float g_b1[HID];
__device__ float g_W2[OUTD * 2 * HID];      // [128, 512] = [W2n | W2h]
__device__ float g_b2[OUTD];

// ---------------------------------------------------------------------------
// Weight prep: concat weights along input dim, sum biases
// ---------------------------------------------------------------------------
__global__ void prep_w1(const float* __restrict__ W1n, const float* __restrict__ b1n,
                        const float* __restrict__ W1h, const float* __restrict__ b1h) {
    int h = blockIdx.x;          // 0..255
    int k = threadIdx.x;         // 0..255
    g_W1[h * 256 + k] = (k < D_IN) ? W1n[h * D_IN + k] : W1h[h * D_IN + (k - D_IN)];
    if (k == 0) g_b1[h] = b1n[h] + b1h[h];
}

__global__ void prep_w2(const float* __restrict__ W2n, const float* __restrict__ b2n,
                        const float* __restrict__ W2h, const float* __restrict__ b2h) {
    int n = blockIdx.x;          // 0..127
    int k = threadIdx.x;         // 0..511
    g_W2[n * 512 + k] = (k < HID) ? W2n[n * HID + k] : W2h[n * HID + (k - HID)];
    if (k == 0) g_b2[n] = b2n[n] + b2h[n];
}

// ---------------------------------------------------------------------------
// Kernel 1: build Acat[i] = [ sum_j x[nbr2[i*16+j]] | x[nodes2[i]] * decay(i) ]
// ---------------------------------------------------------------------------
__global__ void build_acat(const float* __restrict__ x,
                           const int*   __restrict__ nodes2,
                           const int*   __restrict__ nbr2,
                           const float* __restrict__ t2,
                           const float* __restrict__ n_times2,
                           const float* __restrict__ t_kernel) {
    const int i = blockIdx.x;     // row 0..N2-1
    const int d = threadIdx.x;    // 0..127
    const float tk = t_kernel[0];

    const int* nb = nbr2 + (long)i * KF;
    float s = 0.f;
#pragma unroll
    for (int j = 0; j < KF; ++j) {
        s += x[(long)nb[j] * D_IN + d];
    }
    g_Acat[(long)i * 256 + d] = s;

    float dec = __expf(-tk * (t2[i] - n_times2[i]));
    g_Acat[(long)i * 256 + 128 + d] = x[(long)nodes2[i] * D_IN + d] * dec;
}

// ---------------------------------------------------------------------------
// Kernel 2: tf32 tensor-core GEMM-NT + bias + relu.
//   C[M,256] = relu(A[M,256] * W[256,256]^T + bias)
// Block tile 128x128, BK=32, 8 warps (warp tile 64x32), mma.m16n8k8.tf32.
// Smem rows padded to 36 floats -> all fragment LDS are bank-conflict-free
// (bank index = gid*4 + tig = lane id).
// ---------------------------------------------------------------------------
__device__ __forceinline__ float to_tf32(float f) {
    uint32_t u;
    asm("cvt.rna.tf32.f32 %0, %1;" : "=r"(u) : "f"(f));
    return __uint_as_float(u);
}

#define MMA_TF32(d, a, b)                                                     \
    asm volatile(                                                             \
        "mma.sync.aligned.m16n8k8.row.col.f32.tf32.tf32.f32 "                 \
        "{%0,%1,%2,%3}, {%4,%5,%6,%7}, {%8,%9}, {%0,%1,%2,%3};"               \
        : "+f"((d)[0]), "+f"((d)[1]), "+f"((d)[2]), "+f"((d)[3])              \
        : "r"((a)[0]), "r"((a)[1]), "r"((a)[2]), "r"((a)[3]),                 \
          "r"((b)[0]), "r"((b)[1]))

__global__ __launch_bounds__(256, 1) void gemm1_tf32(const float* __restrict__ A,
                                                     const float* __restrict__ W,
                                                     const float* __restrict__ bias,
                                                     float* __restrict__ C) {
    __shared__ float As[128][36];   // [m][k] padded
    __shared__ float Ws[128][36];   // [n][k] padded

    const int tid  = threadIdx.x;
    const int lane = tid & 31;
    const int warp = tid >> 5;
    const int gid  = lane >> 2;     // 0..7
    const int tig  = lane & 3;      // 0..3
    const int wm   = (warp >> 2) << 6;   // 0 / 64
    const int wn   = (warp & 3) << 5;    // 0,32,64,96
    const long bm  = (long)blockIdx.y * 128;
    const int  bn  = blockIdx.x * 128;

    const int lr = tid >> 3;         // 0..31, +32 per chunk
    const int lc = (tid & 7) << 2;   // 0,4,...,28

    float acc[4][4][4];
#pragma unroll
    for (int mt = 0; mt < 4; ++mt)
#pragma unroll
        for (int nt = 0; nt < 4; ++nt)
#pragma unroll
            for (int q = 0; q < 4; ++q) acc[mt][nt][q] = 0.f;

    float4 pa[4], pw[4];
    // prefetch tile 0
#pragma unroll
    for (int p = 0; p < 4; ++p) {
        pa[p] = *(const float4*)&A[(bm + lr + p * 32) * 256 + lc];
        pw[p] = *(const float4*)&W[(long)(bn + lr + p * 32) * 256 + lc];
    }
#pragma unroll
    for (int p = 0; p < 4; ++p) {
        float4 ta = { to_tf32(pa[p].x), to_tf32(pa[p].y), to_tf32(pa[p].z), to_tf32(pa[p].w) };
        *(float4*)&As[lr + p * 32][lc] = ta;
        float4 tw = { to_tf32(pw[p].x), to_tf32(pw[p].y), to_tf32(pw[p].z), to_tf32(pw[p].w) };
        *(float4*)&Ws[lr + p * 32][lc] = tw;
    }
    __syncthreads();

#pragma unroll
    for (int it = 0; it < 8; ++it) {
        if (it < 7) {
            const int k0 = (it + 1) * 32;
#pragma unroll
            for (int p = 0; p < 4; ++p) {
                pa[p] = *(const float4*)&A[(bm + lr + p * 32) * 256 + k0 + lc];
                pw[p] = *(const float4*)&W[(long)(bn + lr + p * 32) * 256 + k0 + lc];
            }
        }

#pragma unroll
        for (int ks = 0; ks < 4; ++ks) {
            const int kk = ks * 8;
            uint32_t af[4][4];
            uint32_t bf[4][2];
#pragma unroll
            for (int mt = 0; mt < 4; ++mt) {
                const int m0 = wm + mt * 16 + gid;
                af[mt][0] = __float_as_uint(As[m0][kk + tig]);
                af[mt][1] = __float_as_uint(As[m0 + 8][kk + tig]);
                af[mt][2] = __float_as_uint(As[m0][kk + tig + 4]);
                af[mt][3] = __float_as_uint(As[m0 + 8][kk + tig + 4]);
            }
#pragma unroll
            for (int nt = 0; nt < 4; ++nt) {
                const int n0 = wn + nt * 8 + gid;
                bf[nt][0] = __float_as_uint(Ws[n0][kk + tig]);
                bf[nt][1] = __float_as_uint(Ws[n0][kk + tig + 4]);
            }
#pragma unroll
            for (int mt = 0; mt < 4; ++mt)
#pragma unroll
                for (int nt = 0; nt < 4; ++nt)
                    MMA_TF32(acc[mt][nt], af[mt], bf[nt]);
        }
        __syncthreads();

        if (it < 7) {
#pragma unroll
            for (int p = 0; p < 4; ++p) {
                float4 ta = { to_tf32(pa[p].x), to_tf32(pa[p].y), to_tf32(pa[p].z), to_tf32(pa[p].w) };
                *(float4*)&As[lr + p * 32][lc] = ta;
                float4 tw = { to_tf32(pw[p].x), to_tf32(pw[p].y), to_tf32(pw[p].z), to_tf32(pw[p].w) };
                *(float4*)&Ws[lr + p * 32][lc] = tw;
            }
            __syncthreads();
        }
    }

    // epilogue: bias + relu, float2 stores
#pragma unroll
    for (int mt = 0; mt < 4; ++mt) {
        const long row0 = bm + wm + mt * 16 + gid;
#pragma unroll
        for (int nt = 0; nt < 4; ++nt) {
            const int col = bn + wn + nt * 8 + 2 * tig;
            const float bv0 = bias[col];
            const float bv1 = bias[col + 1];
            float2 v0, v1;
            v0.x = acc[mt][nt][0] + bv0; v0.x = v0.x > 0.f ? v0.x : 0.f;
            v0.y = acc[mt][nt][1] + bv1; v0.y = v0.y > 0.f ? v0.y : 0.f;
            v1.x = acc[mt][nt][2] + bv0; v1.x = v1.x > 0.f ? v1.x : 0.f;
            v1.y = acc[mt][nt][3] + bv1; v1.y = v1.y > 0.f ? v1.y : 0.f;
            *(float2*)&C[row0 * 256 + col] = v0;
            *(float2*)&C[(row0 + 8) * 256 + col] = v1;
        }
    }
}

// ---------------------------------------------------------------------------
// Kernel 3: build Bcat[b] = [ sum_j h1[b*16+j] | h1[E1+b] * decay2(b) ]
// ---------------------------------------------------------------------------
__global__ void build_bcat(const float* __restrict__ ts,
                           const float* __restrict__ n_times1,
                           const float* __restrict__ t_kernel) {
    const int b = blockIdx.x;     // 0..2047
    const int d = threadIdx.x;    // 0..255
    const float tk = t_kernel[0];

    float s = 0.f;
#pragma unroll
    for (int j = 0; j < KF; ++j) {
        s += g_h1[(long)(b * KF + j) * HID + d];
    }
    g_Bcat[(long)b * 512 + d] = s;

    float dec = __expf(-tk * (ts[b] - n_times1[b]));
    g_Bcat[(long)b * 512 + 256 + d] = g_h1[(long)(E1 + b) * HID + d] * dec;
}

// ---------------------------------------------------------------------------
// Kernel 4: small GEMM  out[2048,128] = relu(Bcat[2048,512] @ W2[128,512]^T + b2)
// ---------------------------------------------------------------------------
__global__ __launch_bounds__(256) void gemm2_relu(float* __restrict__ out) {
    __shared__ float As[16][512];     // 32 KB
    __shared__ float Ws[32][128];     // 16 KB
    const int bm = blockIdx.x * 16;
    const int tid = threadIdx.x;

#pragma unroll
    for (int p = 0; p < 8; ++p) {
        int idx = tid + p * 256;      // float4 index 0..2047
        int r = idx >> 7;             // 0..15
        int c = idx & 127;            // 0..127
        *(float4*)&As[r][c * 4] = *(const float4*)&g_Bcat[(long)(bm + r) * 512 + c * 4];
    }
    __syncthreads();

    const int tx = tid & 127;         // output col
    const int ty = tid >> 7;          // 0..1
    float acc[8];
#pragma unroll
    for (int i = 0; i < 8; ++i) acc[i] = 0.f;

    for (int ch = 0; ch < 16; ++ch) {
#pragma unroll
        for (int p = 0; p < 4; ++p) {
            int idx = tid + p * 256;  // 0..1023
            int n = idx >> 3;         // 0..127
            int k4 = idx & 7;         // 0..7
            float4 v = *(const float4*)&g_W2[(long)n * 512 + ch * 32 + k4 * 4];
            Ws[k4 * 4 + 0][n] = v.x; Ws[k4 * 4 + 1][n] = v.y;
            Ws[k4 * 4 + 2][n] = v.z; Ws[k4 * 4 + 3][n] = v.w;
        }
        __syncthreads();
#pragma unroll
        for (int k = 0; k < 32; ++k) {
            float bv = Ws[k][tx];
#pragma unroll
            for (int i = 0; i < 8; ++i)
                acc[i] += As[ty * 8 + i][ch * 32 + k] * bv;
        }
        __syncthreads();
    }

    float bb = g_b2[tx];
#pragma unroll
    for (int i = 0; i < 8; ++i) {
        float v = acc[i] + bb;
        out[(long)(bm + ty * 8 + i) * OUTD + tx] = v > 0.f ? v : 0.f;
    }
}

// ---------------------------------------------------------------------------
// Launch
// ---------------------------------------------------------------------------
extern "C" void kernel_launch(void* const* d_in, const int* in_sizes, int n_in,
                              void* d_out, int out_size) {
    const float* x        = (const float*)d_in[0];
    const float* ts       = (const float*)d_in[1];
    const float* t2       = (const float*)d_in[2];
    const float* n_times1 = (const float*)d_in[3];
    const float* n_times2 = (const float*)d_in[4];
    const float* W1n      = (const float*)d_in[5];
    const float* b1n      = (const float*)d_in[6];
    const float* W1h      = (const float*)d_in[7];
    const float* b1h      = (const float*)d_in[8];
    const float* W2n      = (const float*)d_in[9];
    const float* b2n      = (const float*)d_in[10];
    const float* W2h      = (const float*)d_in[11];
    const float* b2h      = (const float*)d_in[12];
    const float* t_kernel = (const float*)d_in[13];
    const int*   nodes2   = (const int*)d_in[14];
    const int*   nbr2     = (const int*)d_in[15];
    float* out = (float*)d_out;

    float *pAcat, *pW1, *pb1, *ph1;
    cudaGetSymbolAddress((void**)&pAcat, g_Acat);
    cudaGetSymbolAddress((void**)&pW1, g_W1);
    cudaGetSymbolAddress((void**)&pb1, g_b1);
    cudaGetSymbolAddress((void**)&ph1, g_h1);

    prep_w1<<<HID, 256>>>(W1n, b1n, W1h, b1h);
    prep_w2<<<OUTD, 512>>>(W2n, b2n, W2h, b2h);

    build_acat<<<N2, 128>>>(x, nodes2, nbr2, t2, n_times2, t_kernel);

    dim3 g1(2, N2 / 128);   // (2, 272)
    gemm1_tf32<<<g1, 256>>>(pAcat, pW1, pb1, ph1);

    build_bcat<<<BATCH, 256>>>(ts, n_times1, t_kernel);

    gemm2_relu<<<BATCH / 16, 256>>>(out);
}

// round 6
// speedup vs baseline: 1.8571x; 1.2324x over previous
#include <cuda_runtime.h>
#include <cuda_bf16.h>
#include <cstdint>

// Problem constants (fixed by setup_inputs)
#define NN    200000
#define D_IN  128
#define HID   256
#define OUTD  128
#define BATCH 2048
#define KF    16
#define N2    (BATCH*KF + BATCH)   // 34816
#define E1    (BATCH*KF)           // 32768

// Scratch (device globals; no runtime allocation allowed)
__device__ float g_Acat[N2 * 2 * D_IN];     // [N2, 256] = [agg2 | hn1] (tf32-rounded)
__device__ float g_h1[N2 * HID];            // [N2, 256]
__device__ float g_Bcat[BATCH * 2 * HID];   // [2048, 512] = [agg1 | hn2]
__device__ float g_W1[HID * 2 * D_IN];      // [256, 256] = [W1n | W1h] (tf32-rounded)
__device__ float g_b1[HID];
__device__ float g_W2[OUTD * 2 * HID];      // [128, 512] = [W2n | W2h]
__device__ float g_b2[OUTD];

__device__ __forceinline__ float to_tf32(float f) {
    uint32_t u;
    asm("cvt.rna.tf32.f32 %0, %1;" : "=r"(u) : "f"(f));
    return __uint_as_float(u);
}

// ---------------------------------------------------------------------------
// Weight prep: concat weights along input dim, sum biases.
// W1 stored pre-rounded to tf32 so gemm1 can cp.async raw bits.
// ---------------------------------------------------------------------------
__global__ void prep_w1(const float* __restrict__ W1n, const float* __restrict__ b1n,
                        const float* __restrict__ W1h, const float* __restrict__ b1h) {
    int h = blockIdx.x;          // 0..255
    int k = threadIdx.x;         // 0..255
    float w = (k < D_IN) ? W1n[h * D_IN + k] : W1h[h * D_IN + (k - D_IN)];
    g_W1[h * 256 + k] = to_tf32(w);
    if (k == 0) g_b1[h] = b1n[h] + b1h[h];
}

__global__ void prep_w2(const float* __restrict__ W2n, const float* __restrict__ b2n,
                        const float* __restrict__ W2h, const float* __restrict__ b2h) {
    int n = blockIdx.x;          // 0..127
    int k = threadIdx.x;         // 0..511
    g_W2[n * 512 + k] = (k < HID) ? W2n[n * HID + k] : W2h[n * HID + (k - HID)];
    if (k == 0) g_b2[n] = b2n[n] + b2h[n];
}

// ---------------------------------------------------------------------------
// Kernel 1: build Acat[i] = [ sum_j x[nbr2[i*16+j]] | x[nodes2[i]] * decay(i) ]
// Warp-per-row, float4 loads. Output pre-rounded to tf32.
// grid = N2/8, block = 256 (8 warps)
// ---------------------------------------------------------------------------
__global__ __launch_bounds__(256) void build_acat(const float* __restrict__ x,
                           const int*   __restrict__ nodes2,
                           const int*   __restrict__ nbr2,
                           const float* __restrict__ t2,
                           const float* __restrict__ n_times2,
                           const float* __restrict__ t_kernel) {
    const int warp = threadIdx.x >> 5;
    const int lane = threadIdx.x & 31;
    const long i = (long)blockIdx.x * 8 + warp;   // row 0..N2-1 (N2 = 8*4352)
    const float tk = t_kernel[0];

    // distribute the 16 neighbor indices: one LDG + shfl
    int nbj = nbr2[i * KF + (lane & 15)];

    float4 s = make_float4(0.f, 0.f, 0.f, 0.f);
#pragma unroll
    for (int j = 0; j < KF; ++j) {
        int idx = __shfl_sync(0xffffffffu, nbj, j, 16);
        float4 v = ((const float4*)(x + (long)idx * D_IN))[lane];
        s.x += v.x; s.y += v.y; s.z += v.z; s.w += v.w;
    }
    float4 so = { to_tf32(s.x), to_tf32(s.y), to_tf32(s.z), to_tf32(s.w) };
    ((float4*)(g_Acat + i * 256))[lane] = so;

    float dec = __expf(-tk * (t2[i] - n_times2[i]));
    float4 h = ((const float4*)(x + (long)nodes2[i] * D_IN))[lane];
    float4 ho = { to_tf32(h.x * dec), to_tf32(h.y * dec), to_tf32(h.z * dec), to_tf32(h.w * dec) };
    ((float4*)(g_Acat + i * 256 + 128))[lane] = ho;
}

// ---------------------------------------------------------------------------
// Kernel 2: tf32 tensor-core GEMM-NT + bias + relu, cp.async double-buffered.
//   C[M,256] = relu(A[M,256] * W[256,256]^T + bias)
// Block tile 128x128, BK=32, 8 warps (warp tile 64x32), mma.m16n8k8.tf32.
// Dynamic smem: 2 x (As[128][36] + Ws[128][36]) = 73728 B, 2 CTAs/SM.
// Inputs are pre-rounded to tf32 by producers, so raw-bit copies are exact.
// ---------------------------------------------------------------------------
#define MMA_TF32(d, a, b)                                                     \
    asm volatile(                                                             \
        "mma.sync.aligned.m16n8k8.row.col.f32.tf32.tf32.f32 "                 \
        "{%0,%1,%2,%3}, {%4,%5,%6,%7}, {%8,%9}, {%0,%1,%2,%3};"               \
        : "+f"((d)[0]), "+f"((d)[1]), "+f"((d)[2]), "+f"((d)[3])              \
        : "r"((a)[0]), "r"((a)[1]), "r"((a)[2]), "r"((a)[3]),                 \
          "r"((b)[0]), "r"((b)[1]))

__device__ __forceinline__ void cp_async16(void* smem_ptr, const void* gptr) {
    uint32_t sa = (uint32_t)__cvta_generic_to_shared(smem_ptr);
    asm volatile("cp.async.cg.shared.global [%0], [%1], 16;" :: "r"(sa), "l"(gptr) : "memory");
}

#define TILE_F (128 * 36)

__global__ __launch_bounds__(256, 2) void gemm1_tf32(const float* __restrict__ A,
                                                     const float* __restrict__ W,
                                                     const float* __restrict__ bias,
                                                     float* __restrict__ C) {
    extern __shared__ float smem[];
    float* As = smem;                 // [2][128][36]
    float* Ws = smem + 2 * TILE_F;    // [2][128][36]

    const int tid  = threadIdx.x;
    const int lane = tid & 31;
    const int warp = tid >> 5;
    const int gid  = lane >> 2;     // 0..7
    const int tig  = lane & 3;      // 0..3
    const int wm   = (warp >> 2) << 6;   // 0 / 64
    const int wn   = (warp & 3) << 5;    // 0,32,64,96
    const long bm  = (long)blockIdx.y * 128;
    const int  bn  = blockIdx.x * 128;

    const int lr = tid >> 3;         // 0..31, +32 per chunk
    const int lc = (tid & 7) << 2;   // 0,4,...,28

    float acc[4][4][4];
#pragma unroll
    for (int mt = 0; mt < 4; ++mt)
#pragma unroll
        for (int nt = 0; nt < 4; ++nt)
#pragma unroll
            for (int q = 0; q < 4; ++q) acc[mt][nt][q] = 0.f;

    // prologue: stage 0 into buffer 0
#pragma unroll
    for (int p = 0; p < 4; ++p) {
        int row = lr + p * 32;
        cp_async16(&As[row * 36 + lc], &A[(bm + row) * 256 + lc]);
        cp_async16(&Ws[row * 36 + lc], &W[(long)(bn + row) * 256 + lc]);
    }
    asm volatile("cp.async.commit_group;" ::: "memory");

#pragma unroll
    for (int it = 0; it < 8; ++it) {
        if (it < 7) {
            const int k0 = (it + 1) * 32;
            float* Ad = As + ((it + 1) & 1) * TILE_F;
            float* Wd = Ws + ((it + 1) & 1) * TILE_F;
#pragma unroll
            for (int p = 0; p < 4; ++p) {
                int row = lr + p * 32;
                cp_async16(&Ad[row * 36 + lc], &A[(bm + row) * 256 + k0 + lc]);
                cp_async16(&Wd[row * 36 + lc], &W[(long)(bn + row) * 256 + k0 + lc]);
            }
            asm volatile("cp.async.commit_group;" ::: "memory");
            asm volatile("cp.async.wait_group 1;" ::: "memory");
        } else {
            asm volatile("cp.async.wait_group 0;" ::: "memory");
        }
        __syncthreads();

        const float* Ab = As + (it & 1) * TILE_F;
        const float* Wb = Ws + (it & 1) * TILE_F;
#pragma unroll
        for (int ks = 0; ks < 4; ++ks) {
            const int kk = ks * 8;
            uint32_t af[4][4];
            uint32_t bf[4][2];
#pragma unroll
            for (int mt = 0; mt < 4; ++mt) {
                const int m0 = wm + mt * 16 + gid;
                af[mt][0] = __float_as_uint(Ab[m0 * 36 + kk + tig]);
                af[mt][1] = __float_as_uint(Ab[(m0 + 8) * 36 + kk + tig]);
                af[mt][2] = __float_as_uint(Ab[m0 * 36 + kk + tig + 4]);
                af[mt][3] = __float_as_uint(Ab[(m0 + 8) * 36 + kk + tig + 4]);
            }
#pragma unroll
            for (int nt = 0; nt < 4; ++nt) {
                const int n0 = wn + nt * 8 + gid;
                bf[nt][0] = __float_as_uint(Wb[n0 * 36 + kk + tig]);
                bf[nt][1] = __float_as_uint(Wb[n0 * 36 + kk + tig + 4]);
            }
#pragma unroll
            for (int mt = 0; mt < 4; ++mt)
#pragma unroll
                for (int nt = 0; nt < 4; ++nt)
                    MMA_TF32(acc[mt][nt], af[mt], bf[nt]);
        }
        __syncthreads();
    }

    // epilogue: bias + relu, float2 stores
#pragma unroll
    for (int mt = 0; mt < 4; ++mt) {
        const long row0 = bm + wm + mt * 16 + gid;
#pragma unroll
        for (int nt = 0; nt < 4; ++nt) {
            const int col = bn + wn + nt * 8 + 2 * tig;
            const float bv0 = bias[col];
            const float bv1 = bias[col + 1];
            float2 v0, v1;
            v0.x = acc[mt][nt][0] + bv0; v0.x = v0.x > 0.f ? v0.x : 0.f;
            v0.y = acc[mt][nt][1] + bv1; v0.y = v0.y > 0.f ? v0.y : 0.f;
            v1.x = acc[mt][nt][2] + bv0; v1.x = v1.x > 0.f ? v1.x : 0.f;
            v1.y = acc[mt][nt][3] + bv1; v1.y = v1.y > 0.f ? v1.y : 0.f;
            *(float2*)&C[row0 * 256 + col] = v0;
            *(float2*)&C[(row0 + 8) * 256 + col] = v1;
        }
    }
}

// ---------------------------------------------------------------------------
// Kernel 3: build Bcat[b] = [ sum_j h1[b*16+j] | h1[E1+b] * decay2(b) ]
// ---------------------------------------------------------------------------
__global__ void build_bcat(const float* __restrict__ ts,
                           const float* __restrict__ n_times1,
                           const float* __restrict__ t_kernel) {
    const int b = blockIdx.x;     // 0..2047
    const int d = threadIdx.x;    // 0..255
    const float tk = t_kernel[0];

    float s = 0.f;
#pragma unroll
    for (int j = 0; j < KF; ++j) {
        s += g_h1[(long)(b * KF + j) * HID + d];
    }
    g_Bcat[(long)b * 512 + d] = s;

    float dec = __expf(-tk * (ts[b] - n_times1[b]));
    g_Bcat[(long)b * 512 + 256 + d] = g_h1[(long)(E1 + b) * HID + d] * dec;
}

// ---------------------------------------------------------------------------
// Kernel 4: small GEMM  out[2048,128] = relu(Bcat[2048,512] @ W2[128,512]^T + b2)
// ---------------------------------------------------------------------------
__global__ __launch_bounds__(256) void gemm2_relu(float* __restrict__ out) {
    __shared__ float As[16][512];     // 32 KB
    __shared__ float Ws[32][128];     // 16 KB
    const int bm = blockIdx.x * 16;
    const int tid = threadIdx.x;

#pragma unroll
    for (int p = 0; p < 8; ++p) {
        int idx = tid + p * 256;      // float4 index 0..2047
        int r = idx >> 7;             // 0..15
        int c = idx & 127;            // 0..127
        *(float4*)&As[r][c * 4] = *(const float4*)&g_Bcat[(long)(bm + r) * 512 + c * 4];
    }
    __syncthreads();

    const int tx = tid & 127;         // output col
    const int ty = tid >> 7;          // 0..1
    float acc[8];
#pragma unroll
    for (int i = 0; i < 8; ++i) acc[i] = 0.f;

    for (int ch = 0; ch < 16; ++ch) {
#pragma unroll
        for (int p = 0; p < 4; ++p) {
            int idx = tid + p * 256;  // 0..1023
            int n = idx >> 3;         // 0..127
            int k4 = idx & 7;         // 0..7
            float4 v = *(const float4*)&g_W2[(long)n * 512 + ch * 32 + k4 * 4];
            Ws[k4 * 4 + 0][n] = v.x; Ws[k4 * 4 + 1][n] = v.y;
            Ws[k4 * 4 + 2][n] = v.z; Ws[k4 * 4 + 3][n] = v.w;
        }
        __syncthreads();
#pragma unroll
        for (int k = 0; k < 32; ++k) {
            float bv = Ws[k][tx];
#pragma unroll
            for (int i = 0; i < 8; ++i)
                acc[i] += As[ty * 8 + i][ch * 32 + k] * bv;
        }
        __syncthreads();
    }

    float bb = g_b2[tx];
#pragma unroll
    for (int i = 0; i < 8; ++i) {
        float v = acc[i] + bb;
        out[(long)(bm + ty * 8 + i) * OUTD + tx] = v > 0.f ? v : 0.f;
    }
}

// ---------------------------------------------------------------------------
// Launch
// ---------------------------------------------------------------------------
extern "C" void kernel_launch(void* const* d_in, const int* in_sizes, int n_in,
                              void* d_out, int out_size) {
    const float* x        = (const float*)d_in[0];
    const float* ts       = (const float*)d_in[1];
    const float* t2       = (const float*)d_in[2];
    const float* n_times1 = (const float*)d_in[3];
    const float* n_times2 = (const float*)d_in[4];
    const float* W1n      = (const float*)d_in[5];
    const float* b1n      = (const float*)d_in[6];
    const float* W1h      = (const float*)d_in[7];
    const float* b1h      = (const float*)d_in[8];
    const float* W2n      = (const float*)d_in[9];
    const float* b2n      = (const float*)d_in[10];
    const float* W2h      = (const float*)d_in[11];
    const float* b2h      = (const float*)d_in[12];
    const float* t_kernel = (const float*)d_in[13];
    const int*   nodes2   = (const int*)d_in[14];
    const int*   nbr2     = (const int*)d_in[15];
    float* out = (float*)d_out;

    float *pAcat, *pW1, *pb1, *ph1;
    cudaGetSymbolAddress((void**)&pAcat, g_Acat);
    cudaGetSymbolAddress((void**)&pW1, g_W1);
    cudaGetSymbolAddress((void**)&pb1, g_b1);
    cudaGetSymbolAddress((void**)&ph1, g_h1);

    const int smem1 = 4 * TILE_F * sizeof(float);   // 73728 B
    cudaFuncSetAttribute(gemm1_tf32, cudaFuncAttributeMaxDynamicSharedMemorySize, smem1);

    prep_w1<<<HID, 256>>>(W1n, b1n, W1h, b1h);
    prep_w2<<<OUTD, 512>>>(W2n, b2n, W2h, b2h);

    build_acat<<<N2 / 8, 256>>>(x, nodes2, nbr2, t2, n_times2, t_kernel);

    dim3 g1(2, N2 / 128);   // (2, 272)
    gemm1_tf32<<<g1, 256, smem1>>>(pAcat, pW1, pb1, ph1);

    build_bcat<<<BATCH, 256>>>(ts, n_times1, t_kernel);

    gemm2_relu<<<BATCH / 16, 256>>>(out);
}

// round 9
// speedup vs baseline: 1.9276x; 1.0379x over previous
#include <cuda_runtime.h>
#include <cuda_bf16.h>
#include <cstdint>

// Problem constants (fixed by setup_inputs)
#define NN    200000
#define D_IN  128
#define HID   256
#define OUTD  128
#define BATCH 2048
#define KF    16
#define N2    (BATCH*KF + BATCH)   // 34816
#define E1    (BATCH*KF)           // 32768

// Scratch (device globals; no runtime allocation allowed)
__device__ float g_Acat[N2 * 2 * D_IN];     // [N2, 256] = [agg2 | hn1] (tf32-rounded)
__device__ float g_h1[N2 * HID];            // [N2, 256]
__device__ float g_W1[HID * 2 * D_IN];      // [256, 256] = [W1n | W1h] (tf32-rounded)
__device__ float g_b1[HID];
__device__ float g_W2[OUTD * 2 * HID];      // [128, 512] = [W2n | W2h]
__device__ float g_b2[OUTD];

__device__ __forceinline__ float to_tf32(float f) {
    uint32_t u;
    asm("cvt.rna.tf32.f32 %0, %1;" : "=r"(u) : "f"(f));
    return __uint_as_float(u);
}

// ---------------------------------------------------------------------------
// Weight prep (single launch): grid=256, block=512.
//  block b (all 256 w1-cols by tid<256): W1 row b
//  block b<128 additionally: W2 row b (512 cols by all threads)
// ---------------------------------------------------------------------------
__global__ void prep_w(const float* __restrict__ W1n, const float* __restrict__ b1n,
                       const float* __restrict__ W1h, const float* __restrict__ b1h,
                       const float* __restrict__ W2n, const float* __restrict__ b2n,
                       const float* __restrict__ W2h, const float* __restrict__ b2h) {
    int b = blockIdx.x;
    int k = threadIdx.x;
    if (k < 256) {
        float w = (k < D_IN) ? W1n[b * D_IN + k] : W1h[b * D_IN + (k - D_IN)];
        g_W1[b * 256 + k] = to_tf32(w);
        if (k == 0) g_b1[b] = b1n[b] + b1h[b];
    }
    if (b < OUTD) {
        g_W2[b * 512 + k] = (k < HID) ? W2n[b * HID + k] : W2h[b * HID + (k - HID)];
        if (k == 0) g_b2[b] = b2n[b] + b2h[b];
    }
}

// ---------------------------------------------------------------------------
// Kernel 1: build Acat[i] = [ sum_j x[nbr2[i*16+j]] | x[nodes2[i]] * decay(i) ]
// Warp-per-row, float4 loads. Output pre-rounded to tf32.
// ---------------------------------------------------------------------------
__global__ __launch_bounds__(256) void build_acat(const float* __restrict__ x,
                           const int*   __restrict__ nodes2,
                           const int*   __restrict__ nbr2,
                           const float* __restrict__ t2,
                           const float* __restrict__ n_times2,
                           const float* __restrict__ t_kernel) {
    const int warp = threadIdx.x >> 5;
    const int lane = threadIdx.x & 31;
    const long i = (long)blockIdx.x * 8 + warp;   // row 0..N2-1 (N2 = 8*4352)
    const float tk = t_kernel[0];

    // distribute the 16 neighbor indices: one LDG + shfl
    int nbj = nbr2[i * KF + (lane & 15)];

    float4 s = make_float4(0.f, 0.f, 0.f, 0.f);
#pragma unroll
    for (int j = 0; j < KF; ++j) {
        int idx = __shfl_sync(0xffffffffu, nbj, j, 16);
        float4 v = ((const float4*)(x + (long)idx * D_IN))[lane];
        s.x += v.x; s.y += v.y; s.z += v.z; s.w += v.w;
    }
    float4 so = { to_tf32(s.x), to_tf32(s.y), to_tf32(s.z), to_tf32(s.w) };
    ((float4*)(g_Acat + i * 256))[lane] = so;

    float dec = __expf(-tk * (t2[i] - n_times2[i]));
    float4 h = ((const float4*)(x + (long)nodes2[i] * D_IN))[lane];
    float4 ho = { to_tf32(h.x * dec), to_tf32(h.y * dec), to_tf32(h.z * dec), to_tf32(h.w * dec) };
    ((float4*)(g_Acat + i * 256 + 128))[lane] = ho;
}

// ---------------------------------------------------------------------------
// Kernel 2: tf32 tensor-core GEMM-NT + bias + relu, 3-stage cp.async pipeline,
// ONE __syncthreads per k-iteration.
//   C[M,256] = relu(A[M,256] * W[256,256]^T + bias)
// Block tile 128x128, BK=32, 8 warps (warp tile 64x32), mma.m16n8k8.tf32.
// smem: 3 stages x (As[128][36] + Ws[128][36]) = 110592 B -> 2 CTAs/SM.
// ---------------------------------------------------------------------------
#define MMA_TF32(d, a, b)                                                     \
    asm volatile(                                                             \
        "mma.sync.aligned.m16n8k8.row.col.f32.tf32.tf32.f32 "                 \
        "{%0,%1,%2,%3}, {%4,%5,%6,%7}, {%8,%9}, {%0,%1,%2,%3};"               \
        : "+f"((d)[0]), "+f"((d)[1]), "+f"((d)[2]), "+f"((d)[3])              \
        : "r"((a)[0]), "r"((a)[1]), "r"((a)[2]), "r"((a)[3]),                 \
          "r"((b)[0]), "r"((b)[1]))

__device__ __forceinline__ void cp_async16(void* smem_ptr, const void* gptr) {
    uint32_t sa = (uint32_t)__cvta_generic_to_shared(smem_ptr);
    asm volatile("cp.async.cg.shared.global [%0], [%1], 16;" :: "r"(sa), "l"(gptr) : "memory");
}

#define TILE_F  (128 * 36)        // floats per operand per stage
#define STAGE_F (2 * TILE_F)      // floats per stage (As + Ws)

__global__ __launch_bounds__(256, 2) void gemm1_tf32(const float* __restrict__ A,
                                                     const float* __restrict__ W,
                                                     const float* __restrict__ bias,
                                                     float* __restrict__ C) {
    extern __shared__ float smem[];   // [3][ As 128*36 | Ws 128*36 ]

    const int tid  = threadIdx.x;
    const int lane = tid & 31;
    const int warp = tid >> 5;
    const int gid  = lane >> 2;     // 0..7
    const int tig  = lane & 3;      // 0..3
    const int wm   = (warp >> 2) << 6;   // 0 / 64
    const int wn   = (warp & 3) << 5;    // 0,32,64,96
    const long bm  = (long)blockIdx.y * 128;
    const int  bn  = blockIdx.x * 128;

    const int lr = tid >> 3;         // 0..31, +32 per chunk
    const int lc = (tid & 7) << 2;   // 0,4,...,28

    float acc[4][4][4];
#pragma unroll
    for (int mt = 0; mt < 4; ++mt)
#pragma unroll
        for (int nt = 0; nt < 4; ++nt)
#pragma unroll
            for (int q = 0; q < 4; ++q) acc[mt][nt][q] = 0.f;

    // prologue: stage 0 and 1
#pragma unroll
    for (int s = 0; s < 2; ++s) {
        float* Ad = smem + s * STAGE_F;
        float* Wd = Ad + TILE_F;
        const int k0 = s * 32;
#pragma unroll
        for (int p = 0; p < 4; ++p) {
            int row = lr + p * 32;
            cp_async16(&Ad[row * 36 + lc], &A[(bm + row) * 256 + k0 + lc]);
            cp_async16(&Wd[row * 36 + lc], &W[(long)(bn + row) * 256 + k0 + lc]);
        }
        asm volatile("cp.async.commit_group;" ::: "memory");
    }

#pragma unroll
    for (int it = 0; it < 8; ++it) {
        if (it < 7)
            asm volatile("cp.async.wait_group 1;" ::: "memory");
        else
            asm volatile("cp.async.wait_group 0;" ::: "memory");
        __syncthreads();

        // refill buffer (it+2)%3 == (it-1)%3 -- its last reads finished before
        // the barrier above, so no second barrier is needed.
        if (it + 2 < 8) {
            const int s = (it + 2) % 3;
            float* Ad = smem + s * STAGE_F;
            float* Wd = Ad + TILE_F;
            const int k0 = (it + 2) * 32;
#pragma unroll
            for (int p = 0; p < 4; ++p) {
                int row = lr + p * 32;
                cp_async16(&Ad[row * 36 + lc], &A[(bm + row) * 256 + k0 + lc]);
                cp_async16(&Wd[row * 36 + lc], &W[(long)(bn + row) * 256 + k0 + lc]);
            }
            asm volatile("cp.async.commit_group;" ::: "memory");
        }

        const float* Ab = smem + (it % 3) * STAGE_F;
        const float* Wb = Ab + TILE_F;
#pragma unroll
        for (int ks = 0; ks < 4; ++ks) {
            const int kk = ks * 8;
            uint32_t af[4][4];
            uint32_t bf[4][2];
#pragma unroll
            for (int mt = 0; mt < 4; ++mt) {
                const int m0 = wm + mt * 16 + gid;
                af[mt][0] = __float_as_uint(Ab[m0 * 36 + kk + tig]);
                af[mt][1] = __float_as_uint(Ab[(m0 + 8) * 36 + kk + tig]);
                af[mt][2] = __float_as_uint(Ab[m0 * 36 + kk + tig + 4]);
                af[mt][3] = __float_as_uint(Ab[(m0 + 8) * 36 + kk + tig + 4]);
            }
#pragma unroll
            for (int nt = 0; nt < 4; ++nt) {
                const int n0 = wn + nt * 8 + gid;
                bf[nt][0] = __float_as_uint(Wb[n0 * 36 + kk + tig]);
                bf[nt][1] = __float_as_uint(Wb[n0 * 36 + kk + tig + 4]);
            }
#pragma unroll
            for (int mt = 0; mt < 4; ++mt)
#pragma unroll
                for (int nt = 0; nt < 4; ++nt)
                    MMA_TF32(acc[mt][nt], af[mt], bf[nt]);
        }
    }

    // epilogue: bias + relu, float2 stores
#pragma unroll
    for (int mt = 0; mt < 4; ++mt) {
        const long row0 = bm + wm + mt * 16 + gid;
#pragma unroll
        for (int nt = 0; nt < 4; ++nt) {
            const int col = bn + wn + nt * 8 + 2 * tig;
            const float bv0 = bias[col];
            const float bv1 = bias[col + 1];
            float2 v0, v1;
            v0.x = acc[mt][nt][0] + bv0; v0.x = v0.x > 0.f ? v0.x : 0.f;
            v0.y = acc[mt][nt][1] + bv1; v0.y = v0.y > 0.f ? v0.y : 0.f;
            v1.x = acc[mt][nt][2] + bv0; v1.x = v1.x > 0.f ? v1.x : 0.f;
            v1.y = acc[mt][nt][3] + bv1; v1.y = v1.y > 0.f ? v1.y : 0.f;
            *(float2*)&C[row0 * 256 + col] = v0;
            *(float2*)&C[(row0 + 8) * 256 + col] = v1;
        }
    }
}

// ---------------------------------------------------------------------------
// Kernel 3: fused Bcat-build + GEMM2.
//   Bcat[b] = [ sum_j h1[b*16+j] | h1[E1+b] * decay2(b) ]   (built in smem)
//   out[2048,128] = relu(Bcat @ W2[128,512]^T + b2)
// BM=16 rows per block, full N=128, chunked K (32). 256 threads.
// ---------------------------------------------------------------------------
__global__ __launch_bounds__(256) void gemm2_fused(const float* __restrict__ ts,
                                                   const float* __restrict__ n_times1,
                                                   const float* __restrict__ t_kernel,
                                                   float* __restrict__ out) {
    __shared__ float As[16][512];     // 32 KB (Bcat tile)
    __shared__ float Ws[32][128];     // 16 KB
    const int bm = blockIdx.x * 16;
    const int tid = threadIdx.x;
    const float tk = t_kernel[0];

    // Build A tile: thread (r = tid>>4, c = tid&15) handles row bm+r,
    // float4 columns c*4+p (p=0..3) of each 256-float half.
    {
        const int r = tid >> 4;
        const int c = tid & 15;
        const int b = bm + r;

        float4 s[4];
#pragma unroll
        for (int p = 0; p < 4; ++p) s[p] = make_float4(0.f, 0.f, 0.f, 0.f);
#pragma unroll
        for (int j = 0; j < KF; ++j) {
            const float4* src = (const float4*)(g_h1 + (long)(b * KF + j) * HID);
#pragma unroll
            for (int p = 0; p < 4; ++p) {
                float4 v = src[c * 4 + p];
                s[p].x += v.x; s[p].y += v.y; s[p].z += v.z; s[p].w += v.w;
            }
        }
#pragma unroll
        for (int p = 0; p < 4; ++p)
            ((float4*)As[r])[c * 4 + p] = s[p];

        const float dec = __expf(-tk * (ts[b] - n_times1[b]));
        const float4* self = (const float4*)(g_h1 + (long)(E1 + b) * HID);
#pragma unroll
        for (int p = 0; p < 4; ++p) {
            float4 v = self[c * 4 + p];
            v.x *= dec; v.y *= dec; v.z *= dec; v.w *= dec;
            ((float4*)As[r])[64 + c * 4 + p] = v;
        }
    }
    __syncthreads();

    const int tx = tid & 127;         // output col
    const int ty = tid >> 7;          // 0..1
    float acc[8];
#pragma unroll
    for (int i = 0; i < 8; ++i) acc[i] = 0.f;

    for (int ch = 0; ch < 16; ++ch) {
#pragma unroll
        for (int p = 0; p < 4; ++p) {
            int idx = tid + p * 256;  // 0..1023
            int n = idx >> 3;         // 0..127
            int k4 = idx & 7;         // 0..7
            float4 v = *(const float4*)&g_W2[(long)n * 512 + ch * 32 + k4 * 4];
            Ws[k4 * 4 + 0][n] = v.x; Ws[k4 * 4 + 1][n] = v.y;
            Ws[k4 * 4 + 2][n] = v.z; Ws[k4 * 4 + 3][n] = v.w;
        }
        __syncthreads();
#pragma unroll
        for (int k = 0; k < 32; ++k) {
            float bv = Ws[k][tx];
#pragma unroll
            for (int i = 0; i < 8; ++i)
                acc[i] += As[ty * 8 + i][ch * 32 + k] * bv;
        }
        __syncthreads();
    }

    float bb = g_b2[tx];
#pragma unroll
    for (int i = 0; i < 8; ++i) {
        float v = acc[i] + bb;
        out[(long)(bm + ty * 8 + i) * OUTD + tx] = v > 0.f ? v : 0.f;
    }
}

// ---------------------------------------------------------------------------
// Launch
// ---------------------------------------------------------------------------
extern "C" void kernel_launch(void* const* d_in, const int* in_sizes, int n_in,
                              void* d_out, int out_size) {
    const float* x        = (const float*)d_in[0];
    const float* ts       = (const float*)d_in[1];
    const float* t2       = (const float*)d_in[2];
    const float* n_times1 = (const float*)d_in[3];
    const float* n_times2 = (const float*)d_in[4];
    const float* W1n      = (const float*)d_in[5];
    const float* b1n      = (const float*)d_in[6];
    const float* W1h      = (const float*)d_in[7];
    const float* b1h      = (const float*)d_in[8];
    const float* W2n      = (const float*)d_in[9];
    const float* b2n      = (const float*)d_in[10];
    const float* W2h      = (const float*)d_in[11];
    const float* b2h      = (const float*)d_in[12];
    const float* t_kernel = (const float*)d_in[13];
    const int*   nodes2   = (const int*)d_in[14];
    const int*   nbr2     = (const int*)d_in[15];
    float* out = (float*)d_out;

    float *pAcat, *pW1, *pb1, *ph1;
    cudaGetSymbolAddress((void**)&pAcat, g_Acat);
    cudaGetSymbolAddress((void**)&pW1, g_W1);
    cudaGetSymbolAddress((void**)&pb1, g_b1);
    cudaGetSymbolAddress((void**)&ph1, g_h1);

    const int smem1 = 3 * STAGE_F * sizeof(float);   // 110592 B
    cudaFuncSetAttribute(gemm1_tf32, cudaFuncAttributeMaxDynamicSharedMemorySize, smem1);

    prep_w<<<HID, 512>>>(W1n, b1n, W1h, b1h, W2n, b2n, W2h, b2h);

    build_acat<<<N2 / 8, 256>>>(x, nodes2, nbr2, t2, n_times2, t_kernel);

    dim3 g1(2, N2 / 128);   // (2, 272)
    gemm1_tf32<<<g1, 256, smem1>>>(pAcat, pW1, pb1, ph1);

    gemm2_fused<<<BATCH / 16, 256>>>(ts, n_times1, t_kernel, out);
}

// round 10
// speedup vs baseline: 2.2128x; 1.1479x over previous
#include <cuda_runtime.h>
#include <cuda_bf16.h>
#include <cstdint>

// Problem constants (fixed by setup_inputs)
#define NN    200000
#define D_IN  128
#define HID   256
#define OUTD  128
#define BATCH 2048
#define KF    16
#define N2    (BATCH*KF + BATCH)   // 34816
#define E1    (BATCH*KF)           // 32768

// Scratch (device globals; no runtime allocation allowed)
__device__ float g_Acat[N2 * 2 * D_IN];     // [N2, 256] = [agg2 | hn1] (tf32-rounded)
__device__ float g_h1[N2 * HID];            // [N2, 256]
__device__ float g_W1[HID * 2 * D_IN];      // [256, 256] = [W1n | W1h] (tf32-rounded)
__device__ float g_b1[HID];
__device__ float g_W2[OUTD * 2 * HID];      // [128, 512] = [W2n | W2h] (tf32-rounded)
__device__ float g_b2[OUTD];

__device__ __forceinline__ float to_tf32(float f) {
    uint32_t u;
    asm("cvt.rna.tf32.f32 %0, %1;" : "=r"(u) : "f"(f));
    return __uint_as_float(u);
}

// ---------------------------------------------------------------------------
// Weight prep (single launch): grid=256, block=512.
// ---------------------------------------------------------------------------
__global__ void prep_w(const float* __restrict__ W1n, const float* __restrict__ b1n,
                       const float* __restrict__ W1h, const float* __restrict__ b1h,
                       const float* __restrict__ W2n, const float* __restrict__ b2n,
                       const float* __restrict__ W2h, const float* __restrict__ b2h) {
    int b = blockIdx.x;
    int k = threadIdx.x;
    if (k < 256) {
        float w = (k < D_IN) ? W1n[b * D_IN + k] : W1h[b * D_IN + (k - D_IN)];
        g_W1[b * 256 + k] = to_tf32(w);
        if (k == 0) g_b1[b] = b1n[b] + b1h[b];
    }
    if (b < OUTD) {
        float w = (k < HID) ? W2n[b * HID + k] : W2h[b * HID + (k - HID)];
        g_W2[b * 512 + k] = to_tf32(w);
        if (k == 0) g_b2[b] = b2n[b] + b2h[b];
    }
}

// ---------------------------------------------------------------------------
// Kernel 1: build Acat[i] = [ sum_j x[nbr2[i*16+j]] | x[nodes2[i]] * decay(i) ]
// Warp-per-row, float4 loads. Output pre-rounded to tf32.
// ---------------------------------------------------------------------------
__global__ __launch_bounds__(256) void build_acat(const float* __restrict__ x,
                           const int*   __restrict__ nodes2,
                           const int*   __restrict__ nbr2,
                           const float* __restrict__ t2,
                           const float* __restrict__ n_times2,
                           const float* __restrict__ t_kernel) {
    const int warp = threadIdx.x >> 5;
    const int lane = threadIdx.x & 31;
    const long i = (long)blockIdx.x * 8 + warp;   // row 0..N2-1 (N2 = 8*4352)
    const float tk = t_kernel[0];

    int nbj = nbr2[i * KF + (lane & 15)];

    float4 s = make_float4(0.f, 0.f, 0.f, 0.f);
#pragma unroll
    for (int j = 0; j < KF; ++j) {
        int idx = __shfl_sync(0xffffffffu, nbj, j, 16);
        float4 v = ((const float4*)(x + (long)idx * D_IN))[lane];
        s.x += v.x; s.y += v.y; s.z += v.z; s.w += v.w;
    }
    float4 so = { to_tf32(s.x), to_tf32(s.y), to_tf32(s.z), to_tf32(s.w) };
    ((float4*)(g_Acat + i * 256))[lane] = so;

    float dec = __expf(-tk * (t2[i] - n_times2[i]));
    float4 h = ((const float4*)(x + (long)nodes2[i] * D_IN))[lane];
    float4 ho = { to_tf32(h.x * dec), to_tf32(h.y * dec), to_tf32(h.z * dec), to_tf32(h.w * dec) };
    ((float4*)(g_Acat + i * 256 + 128))[lane] = ho;
}

// ---------------------------------------------------------------------------
// Kernel 2: tf32 tensor-core GEMM-NT + bias + relu, 3-stage cp.async pipeline,
// ONE __syncthreads per k-iteration. (unchanged from R6 — measured good)
// ---------------------------------------------------------------------------
#define MMA_TF32(d, a, b)                                                     \
    asm volatile(                                                             \
        "mma.sync.aligned.m16n8k8.row.col.f32.tf32.tf32.f32 "                 \
        "{%0,%1,%2,%3}, {%4,%5,%6,%7}, {%8,%9}, {%0,%1,%2,%3};"               \
        : "+f"((d)[0]), "+f"((d)[1]), "+f"((d)[2]), "+f"((d)[3])              \
        : "r"((a)[0]), "r"((a)[1]), "r"((a)[2]), "r"((a)[3]),                 \
          "r"((b)[0]), "r"((b)[1]))

__device__ __forceinline__ void cp_async16(void* smem_ptr, const void* gptr) {
    uint32_t sa = (uint32_t)__cvta_generic_to_shared(smem_ptr);
    asm volatile("cp.async.cg.shared.global [%0], [%1], 16;" :: "r"(sa), "l"(gptr) : "memory");
}

#define TILE_F  (128 * 36)        // floats per operand per stage
#define STAGE_F (2 * TILE_F)      // floats per stage (As + Ws)

__global__ __launch_bounds__(256, 2) void gemm1_tf32(const float* __restrict__ A,
                                                     const float* __restrict__ W,
                                                     const float* __restrict__ bias,
                                                     float* __restrict__ C) {
    extern __shared__ float smem[];   // [3][ As 128*36 | Ws 128*36 ]

    const int tid  = threadIdx.x;
    const int lane = tid & 31;
    const int warp = tid >> 5;
    const int gid  = lane >> 2;     // 0..7
    const int tig  = lane & 3;      // 0..3
    const int wm   = (warp >> 2) << 6;   // 0 / 64
    const int wn   = (warp & 3) << 5;    // 0,32,64,96
    const long bm  = (long)blockIdx.y * 128;
    const int  bn  = blockIdx.x * 128;

    const int lr = tid >> 3;         // 0..31, +32 per chunk
    const int lc = (tid & 7) << 2;   // 0,4,...,28

    float acc[4][4][4];
#pragma unroll
    for (int mt = 0; mt < 4; ++mt)
#pragma unroll
        for (int nt = 0; nt < 4; ++nt)
#pragma unroll
            for (int q = 0; q < 4; ++q) acc[mt][nt][q] = 0.f;

    // prologue: stage 0 and 1
#pragma unroll
    for (int s = 0; s < 2; ++s) {
        float* Ad = smem + s * STAGE_F;
        float* Wd = Ad + TILE_F;
        const int k0 = s * 32;
#pragma unroll
        for (int p = 0; p < 4; ++p) {
            int row = lr + p * 32;
            cp_async16(&Ad[row * 36 + lc], &A[(bm + row) * 256 + k0 + lc]);
            cp_async16(&Wd[row * 36 + lc], &W[(long)(bn + row) * 256 + k0 + lc]);
        }
        asm volatile("cp.async.commit_group;" ::: "memory");
    }

#pragma unroll
    for (int it = 0; it < 8; ++it) {
        if (it < 7)
            asm volatile("cp.async.wait_group 1;" ::: "memory");
        else
            asm volatile("cp.async.wait_group 0;" ::: "memory");
        __syncthreads();

        if (it + 2 < 8) {
            const int s = (it + 2) % 3;
            float* Ad = smem + s * STAGE_F;
            float* Wd = Ad + TILE_F;
            const int k0 = (it + 2) * 32;
#pragma unroll
            for (int p = 0; p < 4; ++p) {
                int row = lr + p * 32;
                cp_async16(&Ad[row * 36 + lc], &A[(bm + row) * 256 + k0 + lc]);
                cp_async16(&Wd[row * 36 + lc], &W[(long)(bn + row) * 256 + k0 + lc]);
            }
            asm volatile("cp.async.commit_group;" ::: "memory");
        }

        const float* Ab = smem + (it % 3) * STAGE_F;
        const float* Wb = Ab + TILE_F;
#pragma unroll
        for (int ks = 0; ks < 4; ++ks) {
            const int kk = ks * 8;
            uint32_t af[4][4];
            uint32_t bf[4][2];
#pragma unroll
            for (int mt = 0; mt < 4; ++mt) {
                const int m0 = wm + mt * 16 + gid;
                af[mt][0] = __float_as_uint(Ab[m0 * 36 + kk + tig]);
                af[mt][1] = __float_as_uint(Ab[(m0 + 8) * 36 + kk + tig]);
                af[mt][2] = __float_as_uint(Ab[m0 * 36 + kk + tig + 4]);
                af[mt][3] = __float_as_uint(Ab[(m0 + 8) * 36 + kk + tig + 4]);
            }
#pragma unroll
            for (int nt = 0; nt < 4; ++nt) {
                const int n0 = wn + nt * 8 + gid;
                bf[nt][0] = __float_as_uint(Wb[n0 * 36 + kk + tig]);
                bf[nt][1] = __float_as_uint(Wb[n0 * 36 + kk + tig + 4]);
            }
#pragma unroll
            for (int mt = 0; mt < 4; ++mt)
#pragma unroll
                for (int nt = 0; nt < 4; ++nt)
                    MMA_TF32(acc[mt][nt], af[mt], bf[nt]);
        }
    }

#pragma unroll
    for (int mt = 0; mt < 4; ++mt) {
        const long row0 = bm + wm + mt * 16 + gid;
#pragma unroll
        for (int nt = 0; nt < 4; ++nt) {
            const int col = bn + wn + nt * 8 + 2 * tig;
            const float bv0 = bias[col];
            const float bv1 = bias[col + 1];
            float2 v0, v1;
            v0.x = acc[mt][nt][0] + bv0; v0.x = v0.x > 0.f ? v0.x : 0.f;
            v0.y = acc[mt][nt][1] + bv1; v0.y = v0.y > 0.f ? v0.y : 0.f;
            v1.x = acc[mt][nt][2] + bv0; v1.x = v1.x > 0.f ? v1.x : 0.f;
            v1.y = acc[mt][nt][3] + bv1; v1.y = v1.y > 0.f ? v1.y : 0.f;
            *(float2*)&C[row0 * 256 + col] = v0;
            *(float2*)&C[(row0 + 8) * 256 + col] = v1;
        }
    }
}

// ---------------------------------------------------------------------------
// Kernel 3 (v2): fused Bcat-build + tf32 tensor-core GEMM2.
//   Bcat tile [16,512] built in smem (coalesced, fp32 sum, tf32-rounded once)
//   out[16,128] = relu(Bcat @ W2[128,512]^T + b2) via mma.m16n8k8
// 8 warps: warp w owns N-cols [w*16, w*16+16). K=512 in 16 chunks of 32,
// W2 chunks streamed via 3-stage cp.async ring, one barrier per chunk.
// As row stride 516 floats -> A-fragment LDS conflict-free (bank = lane).
// ---------------------------------------------------------------------------
#define AS2_STRIDE 516
#define AS2_F      (16 * AS2_STRIDE)   // 8256 floats
#define WS2_F      (128 * 36)          // 4608 floats per stage

__global__ __launch_bounds__(256) void gemm2_fused(const float* __restrict__ ts,
                                                   const float* __restrict__ n_times1,
                                                   const float* __restrict__ t_kernel,
                                                   float* __restrict__ out) {
    extern __shared__ float sm2[];      // As[16][516] | Ws[3][128][36]
    float* As = sm2;
    float* Ws = sm2 + AS2_F;

    const int bm   = blockIdx.x * 16;
    const int tid  = threadIdx.x;
    const int lane = tid & 31;
    const int warp = tid >> 5;          // 0..7
    const int gid  = lane >> 2;         // 0..7
    const int tig  = lane & 3;          // 0..3
    const float tk = t_kernel[0];

    // ---- Phase A: build As[16][512] (stride 516), coalesced ----
#pragma unroll
    for (int p = 0; p < 8; ++p) {
        int idx = tid + p * 256;        // 0..2047
        int r = idx >> 7;               // 0..15
        int c = idx & 127;              // float4 col 0..127
        int b = bm + r;
        float4 v;
        if (c < 64) {
            float4 s = make_float4(0.f, 0.f, 0.f, 0.f);
#pragma unroll
            for (int j = 0; j < KF; ++j) {
                float4 t = ((const float4*)(g_h1 + (long)(b * KF + j) * HID))[c];
                s.x += t.x; s.y += t.y; s.z += t.z; s.w += t.w;
            }
            v = s;
        } else {
            float dec = __expf(-tk * (ts[b] - n_times1[b]));
            float4 t = ((const float4*)(g_h1 + (long)(E1 + b) * HID))[c - 64];
            v.x = t.x * dec; v.y = t.y * dec; v.z = t.z * dec; v.w = t.w * dec;
        }
        float4 o = { to_tf32(v.x), to_tf32(v.y), to_tf32(v.z), to_tf32(v.w) };
        *(float4*)&As[r * AS2_STRIDE + c * 4] = o;
    }

    // ---- Phase B prologue: stage W2 chunks 0,1 ----
    // per chunk: Ws[n][36] <- W2[n*512 + ch*32 + k], 1024 float4 / 256 thr = 4
#pragma unroll
    for (int s = 0; s < 2; ++s) {
        float* Wd = Ws + s * WS2_F;
        const int k0 = s * 32;
#pragma unroll
        for (int p = 0; p < 4; ++p) {
            int idx = tid + p * 256;    // 0..1023
            int n = idx >> 3;           // 0..127
            int k4 = (idx & 7) << 2;    // 0,4,...,28
            cp_async16(&Wd[n * 36 + k4], &g_W2[(long)n * 512 + k0 + k4]);
        }
        asm volatile("cp.async.commit_group;" ::: "memory");
    }

    float acc[2][4];
#pragma unroll
    for (int nt = 0; nt < 2; ++nt)
#pragma unroll
        for (int q = 0; q < 4; ++q) acc[nt][q] = 0.f;

    // ---- Phase B mainloop: 16 chunks of K=32 ----
#pragma unroll
    for (int ch = 0; ch < 16; ++ch) {
        if (ch < 15)
            asm volatile("cp.async.wait_group 1;" ::: "memory");
        else
            asm volatile("cp.async.wait_group 0;" ::: "memory");
        __syncthreads();   // also orders Phase-A As writes before first reads

        if (ch + 2 < 16) {
            float* Wd = Ws + ((ch + 2) % 3) * WS2_F;
            const int k0 = (ch + 2) * 32;
#pragma unroll
            for (int p = 0; p < 4; ++p) {
                int idx = tid + p * 256;
                int n = idx >> 3;
                int k4 = (idx & 7) << 2;
                cp_async16(&Wd[n * 36 + k4], &g_W2[(long)n * 512 + k0 + k4]);
            }
            asm volatile("cp.async.commit_group;" ::: "memory");
        }

        const float* Wb = Ws + (ch % 3) * WS2_F;
#pragma unroll
        for (int ks = 0; ks < 4; ++ks) {
            const int ka = ch * 32 + ks * 8;   // global k into As
            const int kw = ks * 8;             // local k into Wb
            uint32_t af[4];
            af[0] = __float_as_uint(As[gid * AS2_STRIDE + ka + tig]);
            af[1] = __float_as_uint(As[(gid + 8) * AS2_STRIDE + ka + tig]);
            af[2] = __float_as_uint(As[gid * AS2_STRIDE + ka + tig + 4]);
            af[3] = __float_as_uint(As[(gid + 8) * AS2_STRIDE + ka + tig + 4]);
#pragma unroll
            for (int nt = 0; nt < 2; ++nt) {
                const int n0 = warp * 16 + nt * 8 + gid;
                uint32_t bf[2];
                bf[0] = __float_as_uint(Wb[n0 * 36 + kw + tig]);
                bf[1] = __float_as_uint(Wb[n0 * 36 + kw + tig + 4]);
                MMA_TF32(acc[nt], af, bf);
            }
        }
    }

    // ---- epilogue: bias + relu ----
#pragma unroll
    for (int nt = 0; nt < 2; ++nt) {
        const int col = warp * 16 + nt * 8 + 2 * tig;
        const float bv0 = g_b2[col];
        const float bv1 = g_b2[col + 1];
        float2 v0, v1;
        v0.x = acc[nt][0] + bv0; v0.x = v0.x > 0.f ? v0.x : 0.f;
        v0.y = acc[nt][1] + bv1; v0.y = v0.y > 0.f ? v0.y : 0.f;
        v1.x = acc[nt][2] + bv0; v1.x = v1.x > 0.f ? v1.x : 0.f;
        v1.y = acc[nt][3] + bv1; v1.y = v1.y > 0.f ? v1.y : 0.f;
        *(float2*)&out[(long)(bm + gid) * OUTD + col] = v0;
        *(float2*)&out[(long)(bm + gid + 8) * OUTD + col] = v1;
    }
}

// ---------------------------------------------------------------------------
// Launch
// ---------------------------------------------------------------------------
extern "C" void kernel_launch(void* const* d_in, const int* in_sizes, int n_in,
                              void* d_out, int out_size) {
    const float* x        = (const float*)d_in[0];
    const float* ts       = (const float*)d_in[1];
    const float* t2       = (const float*)d_in[2];
    const float* n_times1 = (const float*)d_in[3];
    const float* n_times2 = (const float*)d_in[4];
    const float* W1n      = (const float*)d_in[5];
    const float* b1n      = (const float*)d_in[6];
    const float* W1h      = (const float*)d_in[7];
    const float* b1h      = (const float*)d_in[8];
    const float* W2n      = (const float*)d_in[9];
    const float* b2n      = (const float*)d_in[10];
    const float* W2h      = (const float*)d_in[11];
    const float* b2h      = (const float*)d_in[12];
    const float* t_kernel = (const float*)d_in[13];
    const int*   nodes2   = (const int*)d_in[14];
    const int*   nbr2     = (const int*)d_in[15];
    float* out = (float*)d_out;

    float *pAcat, *pW1, *pb1, *ph1;
    cudaGetSymbolAddress((void**)&pAcat, g_Acat);
    cudaGetSymbolAddress((void**)&pW1, g_W1);
    cudaGetSymbolAddress((void**)&pb1, g_b1);
    cudaGetSymbolAddress((void**)&ph1, g_h1);

    const int smem1 = 3 * STAGE_F * sizeof(float);             // 110592 B
    cudaFuncSetAttribute(gemm1_tf32, cudaFuncAttributeMaxDynamicSharedMemorySize, smem1);
    const int smem2 = (AS2_F + 3 * WS2_F) * sizeof(float);     // 88320 B
    cudaFuncSetAttribute(gemm2_fused, cudaFuncAttributeMaxDynamicSharedMemorySize, smem2);

    prep_w<<<HID, 512>>>(W1n, b1n, W1h, b1h, W2n, b2n, W2h, b2h);

    build_acat<<<N2 / 8, 256>>>(x, nodes2, nbr2, t2, n_times2, t_kernel);

    dim3 g1(2, N2 / 128);   // (2, 272)
    gemm1_tf32<<<g1, 256, smem1>>>(pAcat, pW1, pb1, ph1);

    gemm2_fused<<<BATCH / 16, 256, smem2>>>(ts, n_times1, t_kernel, out);
}

// round 12
// speedup vs baseline: 2.6174x; 1.1829x over previous
#include <cuda_runtime.h>
#include <cuda_bf16.h>
#include <cstdint>

// Problem constants (fixed by setup_inputs)
#define NN    200000
#define D_IN  128
#define HID   256
#define OUTD  128
#define BATCH 2048
#define KF    16
#define N2    (BATCH*KF + BATCH)   // 34816
#define E1    (BATCH*KF)           // 32768

// Scratch (device globals; no runtime allocation allowed)
__device__ float g_Acat[N2 * 2 * D_IN];     // [N2, 256] = [agg2 | hn1] (tf32-rounded)
__device__ float g_h1s[BATCH * HID];        // [2048, 256] self rows of h1
__device__ float g_agg1[BATCH * HID];       // [2048, 256] segment sums of h1
__device__ float g_W1[HID * 2 * D_IN];      // [256, 256] = [W1n | W1h] (tf32-rounded)
__device__ float g_b1[HID];
__device__ float g_W2[OUTD * 2 * HID];      // [128, 512] = [W2n | W2h] (tf32-rounded)
__device__ float g_b2[OUTD];

__device__ __forceinline__ float to_tf32(float f) {
    uint32_t u;
    asm("cvt.rna.tf32.f32 %0, %1;" : "=r"(u) : "f"(f));
    return __uint_as_float(u);
}

// ---------------------------------------------------------------------------
// Weight prep (single launch): grid=256, block=512.
// ---------------------------------------------------------------------------
__global__ void prep_w(const float* __restrict__ W1n, const float* __restrict__ b1n,
                       const float* __restrict__ W1h, const float* __restrict__ b1h,
                       const float* __restrict__ W2n, const float* __restrict__ b2n,
                       const float* __restrict__ W2h, const float* __restrict__ b2h) {
    int b = blockIdx.x;
    int k = threadIdx.x;
    if (k < 256) {
        float w = (k < D_IN) ? W1n[b * D_IN + k] : W1h[b * D_IN + (k - D_IN)];
        g_W1[b * 256 + k] = to_tf32(w);
        if (k == 0) g_b1[b] = b1n[b] + b1h[b];
    }
    if (b < OUTD) {
        float w = (k < HID) ? W2n[b * HID + k] : W2h[b * HID + (k - HID)];
        g_W2[b * 512 + k] = to_tf32(w);
        if (k == 0) g_b2[b] = b2n[b] + b2h[b];
    }
}

// ---------------------------------------------------------------------------
// Kernel 1: build Acat[i] = [ sum_j x[nbr2[i*16+j]] | x[nodes2[i]] * decay(i) ]
// Warp-per-row, float4 loads. Output pre-rounded to tf32.
// ---------------------------------------------------------------------------
__global__ __launch_bounds__(256) void build_acat(const float* __restrict__ x,
                           const int*   __restrict__ nodes2,
                           const int*   __restrict__ nbr2,
                           const float* __restrict__ t2,
                           const float* __restrict__ n_times2,
                           const float* __restrict__ t_kernel) {
    const int warp = threadIdx.x >> 5;
    const int lane = threadIdx.x & 31;
    const long i = (long)blockIdx.x * 8 + warp;   // row 0..N2-1 (N2 = 8*4352)
    const float tk = t_kernel[0];

    int nbj = nbr2[i * KF + (lane & 15)];

    float4 s = make_float4(0.f, 0.f, 0.f, 0.f);
#pragma unroll
    for (int j = 0; j < KF; ++j) {
        int idx = __shfl_sync(0xffffffffu, nbj, j, 16);
        float4 v = ((const float4*)(x + (long)idx * D_IN))[lane];
        s.x += v.x; s.y += v.y; s.z += v.z; s.w += v.w;
    }
    float4 so = { to_tf32(s.x), to_tf32(s.y), to_tf32(s.z), to_tf32(s.w) };
    ((float4*)(g_Acat + i * 256))[lane] = so;

    float dec = __expf(-tk * (t2[i] - n_times2[i]));
    float4 h = ((const float4*)(x + (long)nodes2[i] * D_IN))[lane];
    float4 ho = { to_tf32(h.x * dec), to_tf32(h.y * dec), to_tf32(h.z * dec), to_tf32(h.w * dec) };
    ((float4*)(g_Acat + i * 256 + 128))[lane] = ho;
}

// ---------------------------------------------------------------------------
// Kernel 2: tf32 tensor-core GEMM-NT + bias + relu, 3-stage cp.async pipeline.
// Epilogue: for neighbor rows (bm < E1) reduce each 16-row segment
// in-register (shfl over gid) and write only g_agg1[2048,256]; for self rows
// (bm >= E1) write g_h1s[2048,256]. h1 bulk is never materialized.
// ---------------------------------------------------------------------------
#define MMA_TF32(d, a, b)                                                     \
    asm volatile(                                                             \
        "mma.sync.aligned.m16n8k8.row.col.f32.tf32.tf32.f32 "                 \
        "{%0,%1,%2,%3}, {%4,%5,%6,%7}, {%8,%9}, {%0,%1,%2,%3};"               \
        : "+f"((d)[0]), "+f"((d)[1]), "+f"((d)[2]), "+f"((d)[3])              \
        : "r"((a)[0]), "r"((a)[1]), "r"((a)[2]), "r"((a)[3]),                 \
          "r"((b)[0]), "r"((b)[1]))

__device__ __forceinline__ void cp_async16(void* smem_ptr, const void* gptr) {
    uint32_t sa = (uint32_t)__cvta_generic_to_shared(smem_ptr);
    asm volatile("cp.async.cg.shared.global [%0], [%1], 16;" :: "r"(sa), "l"(gptr) : "memory");
}

#define TILE_F  (128 * 36)        // floats per operand per stage
#define STAGE_F (2 * TILE_F)      // floats per stage (As + Ws)

__global__ __launch_bounds__(256, 2) void gemm1_tf32(const float* __restrict__ A,
                                                     const float* __restrict__ W,
                                                     const float* __restrict__ bias,
                                                     float* __restrict__ Cself,
                                                     float* __restrict__ Agg) {
    extern __shared__ float smem[];   // [3][ As 128*36 | Ws 128*36 ]

    const int tid  = threadIdx.x;
    const int lane = tid & 31;
    const int warp = tid >> 5;
    const int gid  = lane >> 2;     // 0..7
    const int tig  = lane & 3;      // 0..3
    const int wm   = (warp >> 2) << 6;   // 0 / 64
    const int wn   = (warp & 3) << 5;    // 0,32,64,96
    const long bm  = (long)blockIdx.y * 128;
    const int  bn  = blockIdx.x * 128;

    const int lr = tid >> 3;         // 0..31, +32 per chunk
    const int lc = (tid & 7) << 2;   // 0,4,...,28

    float acc[4][4][4];
#pragma unroll
    for (int mt = 0; mt < 4; ++mt)
#pragma unroll
        for (int nt = 0; nt < 4; ++nt)
#pragma unroll
            for (int q = 0; q < 4; ++q) acc[mt][nt][q] = 0.f;

    // prologue: stage 0 and 1
#pragma unroll
    for (int s = 0; s < 2; ++s) {
        float* Ad = smem + s * STAGE_F;
        float* Wd = Ad + TILE_F;
        const int k0 = s * 32;
#pragma unroll
        for (int p = 0; p < 4; ++p) {
            int row = lr + p * 32;
            cp_async16(&Ad[row * 36 + lc], &A[(bm + row) * 256 + k0 + lc]);
            cp_async16(&Wd[row * 36 + lc], &W[(long)(bn + row) * 256 + k0 + lc]);
        }
        asm volatile("cp.async.commit_group;" ::: "memory");
    }

#pragma unroll
    for (int it = 0; it < 8; ++it) {
        if (it < 7)
            asm volatile("cp.async.wait_group 1;" ::: "memory");
        else
            asm volatile("cp.async.wait_group 0;" ::: "memory");
        __syncthreads();

        if (it + 2 < 8) {
            const int s = (it + 2) % 3;
            float* Ad = smem + s * STAGE_F;
            float* Wd = Ad + TILE_F;
            const int k0 = (it + 2) * 32;
#pragma unroll
            for (int p = 0; p < 4; ++p) {
                int row = lr + p * 32;
                cp_async16(&Ad[row * 36 + lc], &A[(bm + row) * 256 + k0 + lc]);
                cp_async16(&Wd[row * 36 + lc], &W[(long)(bn + row) * 256 + k0 + lc]);
            }
            asm volatile("cp.async.commit_group;" ::: "memory");
        }

        const float* Ab = smem + (it % 3) * STAGE_F;
        const float* Wb = Ab + TILE_F;
#pragma unroll
        for (int ks = 0; ks < 4; ++ks) {
            const int kk = ks * 8;
            uint32_t af[4][4];
            uint32_t bf[4][2];
#pragma unroll
            for (int mt = 0; mt < 4; ++mt) {
                const int m0 = wm + mt * 16 + gid;
                af[mt][0] = __float_as_uint(Ab[m0 * 36 + kk + tig]);
                af[mt][1] = __float_as_uint(Ab[(m0 + 8) * 36 + kk + tig]);
                af[mt][2] = __float_as_uint(Ab[m0 * 36 + kk + tig + 4]);
                af[mt][3] = __float_as_uint(Ab[(m0 + 8) * 36 + kk + tig + 4]);
            }
#pragma unroll
            for (int nt = 0; nt < 4; ++nt) {
                const int n0 = wn + nt * 8 + gid;
                bf[nt][0] = __float_as_uint(Wb[n0 * 36 + kk + tig]);
                bf[nt][1] = __float_as_uint(Wb[n0 * 36 + kk + tig + 4]);
            }
#pragma unroll
            for (int mt = 0; mt < 4; ++mt)
#pragma unroll
                for (int nt = 0; nt < 4; ++nt)
                    MMA_TF32(acc[mt][nt], af[mt], bf[nt]);
        }
    }

    // epilogue
    const bool selfRows = (bm >= E1);
#pragma unroll
    for (int mt = 0; mt < 4; ++mt) {
#pragma unroll
        for (int nt = 0; nt < 4; ++nt) {
            const int col = bn + wn + nt * 8 + 2 * tig;
            const float bv0 = bias[col];
            const float bv1 = bias[col + 1];
            float a0 = fmaxf(acc[mt][nt][0] + bv0, 0.f);
            float a1 = fmaxf(acc[mt][nt][1] + bv1, 0.f);
            float a2 = fmaxf(acc[mt][nt][2] + bv0, 0.f);
            float a3 = fmaxf(acc[mt][nt][3] + bv1, 0.f);
            if (selfRows) {
                const long r0 = bm + wm + mt * 16 + gid - E1;
                float2 v0 = {a0, a1}, v1 = {a2, a3};
                *(float2*)&Cself[r0 * 256 + col] = v0;
                *(float2*)&Cself[(r0 + 8) * 256 + col] = v1;
            } else {
                // segment = 16 consecutive rows = this warp's mt-th row group
                float s0 = a0 + a2;
                float s1 = a1 + a3;
                s0 += __shfl_xor_sync(0xffffffffu, s0, 4);
                s1 += __shfl_xor_sync(0xffffffffu, s1, 4);
                s0 += __shfl_xor_sync(0xffffffffu, s0, 8);
                s1 += __shfl_xor_sync(0xffffffffu, s1, 8);
                s0 += __shfl_xor_sync(0xffffffffu, s0, 16);
                s1 += __shfl_xor_sync(0xffffffffu, s1, 16);
                if (gid == 0) {
                    const long seg = ((bm + wm) >> 4) + mt;
                    float2 v = {s0, s1};
                    *(float2*)&Agg[seg * 256 + col] = v;
                }
            }
        }
    }
}

// ---------------------------------------------------------------------------
// Kernel 3: gemm2 — Bcat tile from [agg1 | h1s*decay] (coalesced 4 MB total),
// tf32 MMA vs W2 streamed via 3-stage cp.async ring.
// ---------------------------------------------------------------------------
#define AS2_STRIDE 516
#define AS2_F      (16 * AS2_STRIDE)   // 8256 floats
#define WS2_F      (128 * 36)          // 4608 floats per stage

__global__ __launch_bounds__(256) void gemm2_fused(const float* __restrict__ ts,
                                                   const float* __restrict__ n_times1,
                                                   const float* __restrict__ t_kernel,
                                                   float* __restrict__ out) {
    extern __shared__ float sm2[];      // As[16][516] | Ws[3][128][36]
    float* As = sm2;
    float* Ws = sm2 + AS2_F;

    const int bm   = blockIdx.x * 16;
    const int tid  = threadIdx.x;
    const int lane = tid & 31;
    const int warp = tid >> 5;          // 0..7
    const int gid  = lane >> 2;         // 0..7
    const int tig  = lane & 3;          // 0..3
    const float tk = t_kernel[0];

    // ---- Phase A: As[16][512] = [agg1 row | h1s row * decay], coalesced ----
#pragma unroll
    for (int p = 0; p < 8; ++p) {
        int idx = tid + p * 256;        // 0..2047
        int r = idx >> 7;               // 0..15
        int c = idx & 127;              // float4 col 0..127
        int b = bm + r;
        float4 v;
        if (c < 64) {
            v = ((const float4*)(g_agg1 + (long)b * 256))[c];
        } else {
            float dec = __expf(-tk * (ts[b] - n_times1[b]));
            float4 t = ((const float4*)(g_h1s + (long)b * 256))[c - 64];
            v.x = t.x * dec; v.y = t.y * dec; v.z = t.z * dec; v.w = t.w * dec;
        }
        float4 o = { to_tf32(v.x), to_tf32(v.y), to_tf32(v.z), to_tf32(v.w) };
        *(float4*)&As[r * AS2_STRIDE + c * 4] = o;
    }

    // ---- prologue: stage W2 chunks 0,1 ----
#pragma unroll
    for (int s = 0; s < 2; ++s) {
        float* Wd = Ws + s * WS2_F;
        const int k0 = s * 32;
#pragma unroll
        for (int p = 0; p < 4; ++p) {
            int idx = tid + p * 256;    // 0..1023
            int n = idx >> 3;           // 0..127
            int k4 = (idx & 7) << 2;    // 0,4,...,28
            cp_async16(&Wd[n * 36 + k4], &g_W2[(long)n * 512 + k0 + k4]);
        }
        asm volatile("cp.async.commit_group;" ::: "memory");
    }

    float acc[2][4];
#pragma unroll
    for (int nt = 0; nt < 2; ++nt)
#pragma unroll
        for (int q = 0; q < 4; ++q) acc[nt][q] = 0.f;

    // ---- mainloop: 16 chunks of K=32 ----
#pragma unroll
    for (int ch = 0; ch < 16; ++ch) {
        if (ch < 15)
            asm volatile("cp.async.wait_group 1;" ::: "memory");
        else
            asm volatile("cp.async.wait_group 0;" ::: "memory");
        __syncthreads();   // also orders Phase-A As writes before first reads

        if (ch + 2 < 16) {
            float* Wd = Ws + ((ch + 2) % 3) * WS2_F;
            const int k0 = (ch + 2) * 32;
#pragma unroll
            for (int p = 0; p < 4; ++p) {
                int idx = tid + p * 256;
                int n = idx >> 3;
                int k4 = (idx & 7) << 2;
                cp_async16(&Wd[n * 36 + k4], &g_W2[(long)n * 512 + k0 + k4]);
            }
            asm volatile("cp.async.commit_group;" ::: "memory");
        }

        const float* Wb = Ws + (ch % 3) * WS2_F;
#pragma unroll
        for (int ks = 0; ks < 4; ++ks) {
            const int ka = ch * 32 + ks * 8;   // global k into As
            const int kw = ks * 8;             // local k into Wb
            uint32_t af[4];
            af[0] = __float_as_uint(As[gid * AS2_STRIDE + ka + tig]);
            af[1] = __float_as_uint(As[(gid + 8) * AS2_STRIDE + ka + tig]);
            af[2] = __float_as_uint(As[gid * AS2_STRIDE + ka + tig + 4]);
            af[3] = __float_as_uint(As[(gid + 8) * AS2_STRIDE + ka + tig + 4]);
#pragma unroll
            for (int nt = 0; nt < 2; ++nt) {
                const int n0 = warp * 16 + nt * 8 + gid;
                uint32_t bf[2];
                bf[0] = __float_as_uint(Wb[n0 * 36 + kw + tig]);
                bf[1] = __float_as_uint(Wb[n0 * 36 + kw + tig + 4]);
                MMA_TF32(acc[nt], af, bf);
            }
        }
    }

    // ---- epilogue: bias + relu ----
#pragma unroll
    for (int nt = 0; nt < 2; ++nt) {
        const int col = warp * 16 + nt * 8 + 2 * tig;
        const float bv0 = g_b2[col];
        const float bv1 = g_b2[col + 1];
        float2 v0, v1;
        v0.x = acc[nt][0] + bv0; v0.x = v0.x > 0.f ? v0.x : 0.f;
        v0.y = acc[nt][1] + bv1; v0.y = v0.y > 0.f ? v0.y : 0.f;
        v1.x = acc[nt][2] + bv0; v1.x = v1.x > 0.f ? v1.x : 0.f;
        v1.y = acc[nt][3] + bv1; v1.y = v1.y > 0.f ? v1.y : 0.f;
        *(float2*)&out[(long)(bm + gid) * OUTD + col] = v0;
        *(float2*)&out[(long)(bm + gid + 8) * OUTD + col] = v1;
    }
}

// ---------------------------------------------------------------------------
// Launch
// ---------------------------------------------------------------------------
extern "C" void kernel_launch(void* const* d_in, const int* in_sizes, int n_in,
                              void* d_out, int out_size) {
    const float* x        = (const float*)d_in[0];
    const float* ts       = (const float*)d_in[1];
    const float* t2       = (const float*)d_in[2];
    const float* n_times1 = (const float*)d_in[3];
    const float* n_times2 = (const float*)d_in[4];
    const float* W1n      = (const float*)d_in[5];
    const float* b1n      = (const float*)d_in[6];
    const float* W1h      = (const float*)d_in[7];
    const float* b1h      = (const float*)d_in[8];
    const float* W2n      = (const float*)d_in[9];
    const float* b2n      = (const float*)d_in[10];
    const float* W2h      = (const float*)d_in[11];
    const float* b2h      = (const float*)d_in[12];
    const float* t_kernel = (const float*)d_in[13];
    const int*   nodes2   = (const int*)d_in[14];
    const int*   nbr2     = (const int*)d_in[15];
    float* out = (float*)d_out;

    float *pAcat, *pW1, *pb1, *pH1s, *pAgg;
    cudaGetSymbolAddress((void**)&pAcat, g_Acat);
    cudaGetSymbolAddress((void**)&pW1, g_W1);
    cudaGetSymbolAddress((void**)&pb1, g_b1);
    cudaGetSymbolAddress((void**)&pH1s, g_h1s);
    cudaGetSymbolAddress((void**)&pAgg, g_agg1);

    const int smem1 = 3 * STAGE_F * sizeof(float);             // 110592 B
    cudaFuncSetAttribute(gemm1_tf32, cudaFuncAttributeMaxDynamicSharedMemorySize, smem1);
    const int smem2 = (AS2_F + 3 * WS2_F) * sizeof(float);     // 88320 B
    cudaFuncSetAttribute(gemm2_fused, cudaFuncAttributeMaxDynamicSharedMemorySize, smem2);

    prep_w<<<HID, 512>>>(W1n, b1n, W1h, b1h, W2n, b2n, W2h, b2h);

    build_acat<<<N2 / 8, 256>>>(x, nodes2, nbr2, t2, n_times2, t_kernel);

    dim3 g1(2, N2 / 128);   // (2, 272)
    gemm1_tf32<<<g1, 256, smem1>>>(pAcat, pW1, pb1, pH1s, pAgg);

    gemm2_fused<<<BATCH / 16, 256, smem2>>>(ts, n_times1, t_kernel, out);
}

// round 13
// speedup vs baseline: 2.6528x; 1.0136x over previous
#include <cuda_runtime.h>
#include <cuda_bf16.h>
#include <cstdint>

// Problem constants (fixed by setup_inputs)
#define NN    200000
#define D_IN  128
#define HID   256
#define OUTD  128
#define BATCH 2048
#define KF    16
#define N2    (BATCH*KF + BATCH)   // 34816
#define E1    (BATCH*KF)           // 32768

// Scratch (device globals; no runtime allocation allowed)
__device__ float g_Acat[N2 * 2 * D_IN];     // [N2, 256] = [agg2 | hn1] (tf32-rounded)
__device__ float g_h1s[BATCH * HID];        // [2048, 256] self rows of h1
__device__ float g_agg1[BATCH * HID];       // [2048, 256] segment sums of h1
__device__ float g_W1[HID * 2 * D_IN];      // [256, 256] = [W1n | W1h] (tf32-rounded)
__device__ float g_b1[HID];
__device__ float g_W2[OUTD * 2 * HID];      // [128, 512] = [W2n | W2h] (tf32-rounded)
__device__ float g_b2[OUTD];

__device__ __forceinline__ float to_tf32(float f) {
    uint32_t u;
    asm("cvt.rna.tf32.f32 %0, %1;" : "=r"(u) : "f"(f));
    return __uint_as_float(u);
}

// ---------------------------------------------------------------------------
// Weight prep (single launch): grid=256, block=512.
// ---------------------------------------------------------------------------
__global__ void prep_w(const float* __restrict__ W1n, const float* __restrict__ b1n,
                       const float* __restrict__ W1h, const float* __restrict__ b1h,
                       const float* __restrict__ W2n, const float* __restrict__ b2n,
                       const float* __restrict__ W2h, const float* __restrict__ b2h) {
    int b = blockIdx.x;
    int k = threadIdx.x;
    if (k < 256) {
        float w = (k < D_IN) ? W1n[b * D_IN + k] : W1h[b * D_IN + (k - D_IN)];
        g_W1[b * 256 + k] = to_tf32(w);
        if (k == 0) g_b1[b] = b1n[b] + b1h[b];
    }
    if (b < OUTD) {
        float w = (k < HID) ? W2n[b * HID + k] : W2h[b * HID + (k - HID)];
        g_W2[b * 512 + k] = to_tf32(w);
        if (k == 0) g_b2[b] = b2n[b] + b2h[b];
    }
}

// ---------------------------------------------------------------------------
// Kernel 1: build Acat[i] = [ sum_j x[nbr2[i*16+j]] | x[nodes2[i]] * decay(i) ]
// Warp-per-row, float4 loads. Output pre-rounded to tf32.
// ---------------------------------------------------------------------------
__global__ __launch_bounds__(256) void build_acat(const float* __restrict__ x,
                           const int*   __restrict__ nodes2,
                           const int*   __restrict__ nbr2,
                           const float* __restrict__ t2,
                           const float* __restrict__ n_times2,
                           const float* __restrict__ t_kernel) {
    const int warp = threadIdx.x >> 5;
    const int lane = threadIdx.x & 31;
    const long i = (long)blockIdx.x * 8 + warp;   // row 0..N2-1 (N2 = 8*4352)
    const float tk = t_kernel[0];

    int nbj = nbr2[i * KF + (lane & 15)];

    float4 s = make_float4(0.f, 0.f, 0.f, 0.f);
#pragma unroll
    for (int j = 0; j < KF; ++j) {
        int idx = __shfl_sync(0xffffffffu, nbj, j, 16);
        float4 v = ((const float4*)(x + (long)idx * D_IN))[lane];
        s.x += v.x; s.y += v.y; s.z += v.z; s.w += v.w;
    }
    float4 so = { to_tf32(s.x), to_tf32(s.y), to_tf32(s.z), to_tf32(s.w) };
    ((float4*)(g_Acat + i * 256))[lane] = so;

    float dec = __expf(-tk * (t2[i] - n_times2[i]));
    float4 h = ((const float4*)(x + (long)nodes2[i] * D_IN))[lane];
    float4 ho = { to_tf32(h.x * dec), to_tf32(h.y * dec), to_tf32(h.z * dec), to_tf32(h.w * dec) };
    ((float4*)(g_Acat + i * 256 + 128))[lane] = ho;
}

// ---------------------------------------------------------------------------
// Kernel 2: tf32 tensor-core GEMM-NT + bias + relu, 3-stage cp.async pipeline.
// Epilogue: for neighbor rows (bm < E1) reduce each 16-row segment
// in-register (shfl over gid) and write only g_agg1[2048,256]; for self rows
// (bm >= E1) write g_h1s[2048,256]. h1 bulk is never materialized.
// ---------------------------------------------------------------------------
#define MMA_TF32(d, a, b)                                                     \
    asm volatile(                                                             \
        "mma.sync.aligned.m16n8k8.row.col.f32.tf32.tf32.f32 "                 \
        "{%0,%1,%2,%3}, {%4,%5,%6,%7}, {%8,%9}, {%0,%1,%2,%3};"               \
        : "+f"((d)[0]), "+f"((d)[1]), "+f"((d)[2]), "+f"((d)[3])              \
        : "r"((a)[0]), "r"((a)[1]), "r"((a)[2]), "r"((a)[3]),                 \
          "r"((b)[0]), "r"((b)[1]))

__device__ __forceinline__ void cp_async16(void* smem_ptr, const void* gptr) {
    uint32_t sa = (uint32_t)__cvta_generic_to_shared(smem_ptr);
    asm volatile("cp.async.cg.shared.global [%0], [%1], 16;" :: "r"(sa), "l"(gptr) : "memory");
}

#define TILE_F  (128 * 36)        // floats per operand per stage
#define STAGE_F (2 * TILE_F)      // floats per stage (As + Ws)

__global__ __launch_bounds__(256, 2) void gemm1_tf32(const float* __restrict__ A,
                                                     const float* __restrict__ W,
                                                     const float* __restrict__ bias,
                                                     float* __restrict__ Cself,
                                                     float* __restrict__ Agg) {
    extern __shared__ float smem[];   // [3][ As 128*36 | Ws 128*36 ]

    const int tid  = threadIdx.x;
    const int lane = tid & 31;
    const int warp = tid >> 5;
    const int gid  = lane >> 2;     // 0..7
    const int tig  = lane & 3;      // 0..3
    const int wm   = (warp >> 2) << 6;   // 0 / 64
    const int wn   = (warp & 3) << 5;    // 0,32,64,96
    const long bm  = (long)blockIdx.y * 128;
    const int  bn  = blockIdx.x * 128;

    const int lr = tid >> 3;         // 0..31, +32 per chunk
    const int lc = (tid & 7) << 2;   // 0,4,...,28

    float acc[4][4][4];
#pragma unroll
    for (int mt = 0; mt < 4; ++mt)
#pragma unroll
        for (int nt = 0; nt < 4; ++nt)
#pragma unroll
            for (int q = 0; q < 4; ++q) acc[mt][nt][q] = 0.f;

    // prologue: stage 0 and 1
#pragma unroll
    for (int s = 0; s < 2; ++s) {
        float* Ad = smem + s * STAGE_F;
        float* Wd = Ad + TILE_F;
        const int k0 = s * 32;
#pragma unroll
        for (int p = 0; p < 4; ++p) {
            int row = lr + p * 32;
            cp_async16(&Ad[row * 36 + lc], &A[(bm + row) * 256 + k0 + lc]);
            cp_async16(&Wd[row * 36 + lc], &W[(long)(bn + row) * 256 + k0 + lc]);
        }
        asm volatile("cp.async.commit_group;" ::: "memory");
    }

#pragma unroll
    for (int it = 0; it < 8; ++it) {
        if (it < 7)
            asm volatile("cp.async.wait_group 1;" ::: "memory");
        else
            asm volatile("cp.async.wait_group 0;" ::: "memory");
        __syncthreads();

        if (it + 2 < 8) {
            const int s = (it + 2) % 3;
            float* Ad = smem + s * STAGE_F;
            float* Wd = Ad + TILE_F;
            const int k0 = (it + 2) * 32;
#pragma unroll
            for (int p = 0; p < 4; ++p) {
                int row = lr + p * 32;
                cp_async16(&Ad[row * 36 + lc], &A[(bm + row) * 256 + k0 + lc]);
                cp_async16(&Wd[row * 36 + lc], &W[(long)(bn + row) * 256 + k0 + lc]);
            }
            asm volatile("cp.async.commit_group;" ::: "memory");
        }

        const float* Ab = smem + (it % 3) * STAGE_F;
        const float* Wb = Ab + TILE_F;
#pragma unroll
        for (int ks = 0; ks < 4; ++ks) {
            const int kk = ks * 8;
            uint32_t af[4][4];
            uint32_t bf[4][2];
#pragma unroll
            for (int mt = 0; mt < 4; ++mt) {
                const int m0 = wm + mt * 16 + gid;
                af[mt][0] = __float_as_uint(Ab[m0 * 36 + kk + tig]);
                af[mt][1] = __float_as_uint(Ab[(m0 + 8) * 36 + kk + tig]);
                af[mt][2] = __float_as_uint(Ab[m0 * 36 + kk + tig + 4]);
                af[mt][3] = __float_as_uint(Ab[(m0 + 8) * 36 + kk + tig + 4]);
            }
#pragma unroll
            for (int nt = 0; nt < 4; ++nt) {
                const int n0 = wn + nt * 8 + gid;
                bf[nt][0] = __float_as_uint(Wb[n0 * 36 + kk + tig]);
                bf[nt][1] = __float_as_uint(Wb[n0 * 36 + kk + tig + 4]);
            }
#pragma unroll
            for (int mt = 0; mt < 4; ++mt)
#pragma unroll
                for (int nt = 0; nt < 4; ++nt)
                    MMA_TF32(acc[mt][nt], af[mt], bf[nt]);
        }
    }

    // epilogue
    const bool selfRows = (bm >= E1);
#pragma unroll
    for (int mt = 0; mt < 4; ++mt) {
#pragma unroll
        for (int nt = 0; nt < 4; ++nt) {
            const int col = bn + wn + nt * 8 + 2 * tig;
            const float bv0 = bias[col];
            const float bv1 = bias[col + 1];
            float a0 = fmaxf(acc[mt][nt][0] + bv0, 0.f);
            float a1 = fmaxf(acc[mt][nt][1] + bv1, 0.f);
            float a2 = fmaxf(acc[mt][nt][2] + bv0, 0.f);
            float a3 = fmaxf(acc[mt][nt][3] + bv1, 0.f);
            if (selfRows) {
                const long r0 = bm + wm + mt * 16 + gid - E1;
                float2 v0 = {a0, a1}, v1 = {a2, a3};
                *(float2*)&Cself[r0 * 256 + col] = v0;
                *(float2*)&Cself[(r0 + 8) * 256 + col] = v1;
            } else {
                // segment = 16 consecutive rows = this warp's mt-th row group
                float s0 = a0 + a2;
                float s1 = a1 + a3;
                s0 += __shfl_xor_sync(0xffffffffu, s0, 4);
                s1 += __shfl_xor_sync(0xffffffffu, s1, 4);
                s0 += __shfl_xor_sync(0xffffffffu, s0, 8);
                s1 += __shfl_xor_sync(0xffffffffu, s1, 8);
                s0 += __shfl_xor_sync(0xffffffffu, s0, 16);
                s1 += __shfl_xor_sync(0xffffffffu, s1, 16);
                if (gid == 0) {
                    const long seg = ((bm + wm) >> 4) + mt;
                    float2 v = {s0, s1};
                    *(float2*)&Agg[seg * 256 + col] = v;
                }
            }
        }
    }
}

// ---------------------------------------------------------------------------
// Kernel 3: gemm2 — Bcat tile from [agg1 | h1s*decay] (coalesced 4 MB total),
// tf32 MMA vs W2 streamed via 3-stage cp.async ring.
// ---------------------------------------------------------------------------
#define AS2_STRIDE 516
#define AS2_F      (16 * AS2_STRIDE)   // 8256 floats
#define WS2_F      (128 * 36)          // 4608 floats per stage

__global__ __launch_bounds__(256) void gemm2_fused(const float* __restrict__ ts,
                                                   const float* __restrict__ n_times1,
                                                   const float* __restrict__ t_kernel,
                                                   float* __restrict__ out) {
    extern __shared__ float sm2[];      // As[16][516] | Ws[3][128][36]
    float* As = sm2;
    float* Ws = sm2 + AS2_F;

    const int bm   = blockIdx.x * 16;
    const int tid  = threadIdx.x;
    const int lane = tid & 31;
    const int warp = tid >> 5;          // 0..7
    const int gid  = lane >> 2;         // 0..7
    const int tig  = lane & 3;          // 0..3
    const float tk = t_kernel[0];

    // ---- Phase A: As[16][512] = [agg1 row | h1s row * decay], coalesced ----
#pragma unroll
    for (int p = 0; p < 8; ++p) {
        int idx = tid + p * 256;        // 0..2047
        int r = idx >> 7;               // 0..15
        int c = idx & 127;              // float4 col 0..127
        int b = bm + r;
        float4 v;
        if (c < 64) {
            v = ((const float4*)(g_agg1 + (long)b * 256))[c];
        } else {
            float dec = __expf(-tk * (ts[b] - n_times1[b]));
            float4 t = ((const float4*)(g_h1s + (long)b * 256))[c - 64];
            v.x = t.x * dec; v.y = t.y * dec; v.z = t.z * dec; v.w = t.w * dec;
        }
        float4 o = { to_tf32(v.x), to_tf32(v.y), to_tf32(v.z), to_tf32(v.w) };
        *(float4*)&As[r * AS2_STRIDE + c * 4] = o;
    }

    // ---- prologue: stage W2 chunks 0,1 ----
#pragma unroll
    for (int s = 0; s < 2; ++s) {
        float* Wd = Ws + s * WS2_F;
        const int k0 = s * 32;
#pragma unroll
        for (int p = 0; p < 4; ++p) {
            int idx = tid + p * 256;    // 0..1023
            int n = idx >> 3;           // 0..127
            int k4 = (idx & 7) << 2;    // 0,4,...,28
            cp_async16(&Wd[n * 36 + k4], &g_W2[(long)n * 512 + k0 + k4]);
        }
        asm volatile("cp.async.commit_group;" ::: "memory");
    }

    float acc[2][4];
#pragma unroll
    for (int nt = 0; nt < 2; ++nt)
#pragma unroll
        for (int q = 0; q < 4; ++q) acc[nt][q] = 0.f;

    // ---- mainloop: 16 chunks of K=32 ----
#pragma unroll
    for (int ch = 0; ch < 16; ++ch) {
        if (ch < 15)
            asm volatile("cp.async.wait_group 1;" ::: "memory");
        else
            asm volatile("cp.async.wait_group 0;" ::: "memory");
        __syncthreads();   // also orders Phase-A As writes before first reads

        if (ch + 2 < 16) {
            float* Wd = Ws + ((ch + 2) % 3) * WS2_F;
            const int k0 = (ch + 2) * 32;
#pragma unroll
            for (int p = 0; p < 4; ++p) {
                int idx = tid + p * 256;
                int n = idx >> 3;
                int k4 = (idx & 7) << 2;
                cp_async16(&Wd[n * 36 + k4], &g_W2[(long)n * 512 + k0 + k4]);
            }
            asm volatile("cp.async.commit_group;" ::: "memory");
        }

        const float* Wb = Ws + (ch % 3) * WS2_F;
#pragma unroll
        for (int ks = 0; ks < 4; ++ks) {
            const int ka = ch * 32 + ks * 8;   // global k into As
            const int kw = ks * 8;             // local k into Wb
            uint32_t af[4];
            af[0] = __float_as_uint(As[gid * AS2_STRIDE + ka + tig]);
            af[1] = __float_as_uint(As[(gid + 8) * AS2_STRIDE + ka + tig]);
            af[2] = __float_as_uint(As[gid * AS2_STRIDE + ka + tig + 4]);
            af[3] = __float_as_uint(As[(gid + 8) * AS2_STRIDE + ka + tig + 4]);
#pragma unroll
            for (int nt = 0; nt < 2; ++nt) {
                const int n0 = warp * 16 + nt * 8 + gid;
                uint32_t bf[2];
                bf[0] = __float_as_uint(Wb[n0 * 36 + kw + tig]);
                bf[1] = __float_as_uint(Wb[n0 * 36 + kw + tig + 4]);
                MMA_TF32(acc[nt], af, bf);
            }
        }
    }

    // ---- epilogue: bias + relu ----
#pragma unroll
    for (int nt = 0; nt < 2; ++nt) {
        const int col = warp * 16 + nt * 8 + 2 * tig;
        const float bv0 = g_b2[col];
        const float bv1 = g_b2[col + 1];
        float2 v0, v1;
        v0.x = acc[nt][0] + bv0; v0.x = v0.x > 0.f ? v0.x : 0.f;
        v0.y = acc[nt][1] + bv1; v0.y = v0.y > 0.f ? v0.y : 0.f;
        v1.x = acc[nt][2] + bv0; v1.x = v1.x > 0.f ? v1.x : 0.f;
        v1.y = acc[nt][3] + bv1; v1.y = v1.y > 0.f ? v1.y : 0.f;
        *(float2*)&out[(long)(bm + gid) * OUTD + col] = v0;
        *(float2*)&out[(long)(bm + gid + 8) * OUTD + col] = v1;
    }
}

// ---------------------------------------------------------------------------
// Launch
// ---------------------------------------------------------------------------
extern "C" void kernel_launch(void* const* d_in, const int* in_sizes, int n_in,
                              void* d_out, int out_size) {
    const float* x        = (const float*)d_in[0];
    const float* ts       = (const float*)d_in[1];
    const float* t2       = (const float*)d_in[2];
    const float* n_times1 = (const float*)d_in[3];
    const float* n_times2 = (const float*)d_in[4];
    const float* W1n      = (const float*)d_in[5];
    const float* b1n      = (const float*)d_in[6];
    const float* W1h      = (const float*)d_in[7];
    const float* b1h      = (const float*)d_in[8];
    const float* W2n      = (const float*)d_in[9];
    const float* b2n      = (const float*)d_in[10];
    const float* W2h      = (const float*)d_in[11];
    const float* b2h      = (const float*)d_in[12];
    const float* t_kernel = (const float*)d_in[13];
    const int*   nodes2   = (const int*)d_in[14];
    const int*   nbr2     = (const int*)d_in[15];
    float* out = (float*)d_out;

    float *pAcat, *pW1, *pb1, *pH1s, *pAgg;
    cudaGetSymbolAddress((void**)&pAcat, g_Acat);
    cudaGetSymbolAddress((void**)&pW1, g_W1);
    cudaGetSymbolAddress((void**)&pb1, g_b1);
    cudaGetSymbolAddress((void**)&pH1s, g_h1s);
    cudaGetSymbolAddress((void**)&pAgg, g_agg1);

    const int smem1 = 3 * STAGE_F * sizeof(float);             // 110592 B
    cudaFuncSetAttribute(gemm1_tf32, cudaFuncAttributeMaxDynamicSharedMemorySize, smem1);
    const int smem2 = (AS2_F + 3 * WS2_F) * sizeof(float);     // 88320 B
    cudaFuncSetAttribute(gemm2_fused, cudaFuncAttributeMaxDynamicSharedMemorySize, smem2);

    prep_w<<<HID, 512>>>(W1n, b1n, W1h, b1h, W2n, b2n, W2h, b2h);

    build_acat<<<N2 / 8, 256>>>(x, nodes2, nbr2, t2, n_times2, t_kernel);

    dim3 g1(2, N2 / 128);   // (2, 272)
    gemm1_tf32<<<g1, 256, smem1>>>(pAcat, pW1, pb1, pH1s, pAgg);

    gemm2_fused<<<BATCH / 16, 256, smem2>>>(ts, n_times1, t_kernel, out);
}

// round 14
// speedup vs baseline: 2.7966x; 1.0542x over previous
#include <cuda_runtime.h>
#include <cuda_bf16.h>
#include <cstdint>

// Problem constants (fixed by setup_inputs)
#define NN    200000
#define D_IN  128
#define HID   256
#define OUTD  128
#define BATCH 2048
#define KF    16
#define N2    (BATCH*KF + BATCH)   // 34816
#define E1    (BATCH*KF)           // 32768

// Scratch (device globals; no runtime allocation allowed)
__device__ float g_Acat[N2 * 2 * D_IN];     // [N2, 256] = [agg2 | hn1] (tf32-rounded)
__device__ float g_h1s[BATCH * HID];        // [2048, 256] self rows of h1
__device__ float g_agg1[BATCH * HID];       // [2048, 256] segment sums of h1
__device__ float g_W1[HID * 2 * D_IN];      // [256, 256] = [W1n | W1h] (tf32-rounded)
__device__ float g_b1[HID];
__device__ float g_W2[OUTD * 2 * HID];      // [128, 512] = [W2n | W2h] (tf32-rounded)
__device__ float g_b2[OUTD];

__device__ __forceinline__ float to_tf32(float f) {
    uint32_t u;
    asm("cvt.rna.tf32.f32 %0, %1;" : "=r"(u) : "f"(f));
    return __uint_as_float(u);
}

// ---------------------------------------------------------------------------
// Kernel 1: weight prep (blocks < 256) + build Acat (all 4352 blocks).
// Acat[i] = [ sum_j x[nbr2[i*16+j]] | x[nodes2[i]] * decay(i) ], tf32-rounded.
// Warp-per-row, float4 loads.
// ---------------------------------------------------------------------------
__global__ __launch_bounds__(256) void build_acat(const float* __restrict__ x,
                           const int*   __restrict__ nodes2,
                           const int*   __restrict__ nbr2,
                           const float* __restrict__ t2,
                           const float* __restrict__ n_times2,
                           const float* __restrict__ t_kernel,
                           const float* __restrict__ W1n, const float* __restrict__ b1n,
                           const float* __restrict__ W1h, const float* __restrict__ b1h,
                           const float* __restrict__ W2n, const float* __restrict__ b2n,
                           const float* __restrict__ W2h, const float* __restrict__ b2h) {
    // ---- folded weight prep (consumed only by later kernels; no sync needed)
    if (blockIdx.x < HID) {
        const int b = blockIdx.x;
        const int k = threadIdx.x;
        float w = (k < D_IN) ? W1n[b * D_IN + k] : W1h[b * D_IN + (k - D_IN)];
        g_W1[b * 256 + k] = to_tf32(w);
        if (k == 0) g_b1[b] = b1n[b] + b1h[b];
        if (b < OUTD) {
#pragma unroll
            for (int kk = k; kk < 512; kk += 256) {
                float w2 = (kk < HID) ? W2n[b * HID + kk] : W2h[b * HID + (kk - HID)];
                g_W2[b * 512 + kk] = to_tf32(w2);
            }
            if (k == 0) g_b2[b] = b2n[b] + b2h[b];
        }
    }

    const int warp = threadIdx.x >> 5;
    const int lane = threadIdx.x & 31;
    const long i = (long)blockIdx.x * 8 + warp;   // row 0..N2-1 (N2 = 8*4352)
    const float tk = t_kernel[0];

    int nbj = nbr2[i * KF + (lane & 15)];

    float4 s = make_float4(0.f, 0.f, 0.f, 0.f);
#pragma unroll
    for (int j = 0; j < KF; ++j) {
        int idx = __shfl_sync(0xffffffffu, nbj, j, 16);
        float4 v = ((const float4*)(x + (long)idx * D_IN))[lane];
        s.x += v.x; s.y += v.y; s.z += v.z; s.w += v.w;
    }
    float4 so = { to_tf32(s.x), to_tf32(s.y), to_tf32(s.z), to_tf32(s.w) };
    ((float4*)(g_Acat + i * 256))[lane] = so;

    float dec = __expf(-tk * (t2[i] - n_times2[i]));
    float4 h = ((const float4*)(x + (long)nodes2[i] * D_IN))[lane];
    float4 ho = { to_tf32(h.x * dec), to_tf32(h.y * dec), to_tf32(h.z * dec), to_tf32(h.w * dec) };
    ((float4*)(g_Acat + i * 256 + 128))[lane] = ho;
}

// ---------------------------------------------------------------------------
// Kernel 2: tf32 tensor-core GEMM-NT + bias + relu, 3-stage cp.async pipeline.
// Epilogue: neighbor rows (bm < E1) -> in-register 16-row segment sums into
// g_agg1; self rows (bm >= E1) -> g_h1s. (unchanged from R13 — measured good)
// ---------------------------------------------------------------------------
#define MMA_TF32(d, a, b)                                                     \
    asm volatile(                                                             \
        "mma.sync.aligned.m16n8k8.row.col.f32.tf32.tf32.f32 "                 \
        "{%0,%1,%2,%3}, {%4,%5,%6,%7}, {%8,%9}, {%0,%1,%2,%3};"               \
        : "+f"((d)[0]), "+f"((d)[1]), "+f"((d)[2]), "+f"((d)[3])              \
        : "r"((a)[0]), "r"((a)[1]), "r"((a)[2]), "r"((a)[3]),                 \
          "r"((b)[0]), "r"((b)[1]))

__device__ __forceinline__ void cp_async16(void* smem_ptr, const void* gptr) {
    uint32_t sa = (uint32_t)__cvta_generic_to_shared(smem_ptr);
    asm volatile("cp.async.cg.shared.global [%0], [%1], 16;" :: "r"(sa), "l"(gptr) : "memory");
}

#define TILE_F  (128 * 36)        // floats per operand per stage
#define STAGE_F (2 * TILE_F)      // floats per stage (As + Ws)

__global__ __launch_bounds__(256, 2) void gemm1_tf32(const float* __restrict__ A,
                                                     const float* __restrict__ W,
                                                     const float* __restrict__ bias,
                                                     float* __restrict__ Cself,
                                                     float* __restrict__ Agg) {
    extern __shared__ float smem[];   // [3][ As 128*36 | Ws 128*36 ]

    const int tid  = threadIdx.x;
    const int lane = tid & 31;
    const int warp = tid >> 5;
    const int gid  = lane >> 2;     // 0..7
    const int tig  = lane & 3;      // 0..3
    const int wm   = (warp >> 2) << 6;   // 0 / 64
    const int wn   = (warp & 3) << 5;    // 0,32,64,96
    const long bm  = (long)blockIdx.y * 128;
    const int  bn  = blockIdx.x * 128;

    const int lr = tid >> 3;         // 0..31, +32 per chunk
    const int lc = (tid & 7) << 2;   // 0,4,...,28

    float acc[4][4][4];
#pragma unroll
    for (int mt = 0; mt < 4; ++mt)
#pragma unroll
        for (int nt = 0; nt < 4; ++nt)
#pragma unroll
            for (int q = 0; q < 4; ++q) acc[mt][nt][q] = 0.f;

    // prologue: stage 0 and 1
#pragma unroll
    for (int s = 0; s < 2; ++s) {
        float* Ad = smem + s * STAGE_F;
        float* Wd = Ad + TILE_F;
        const int k0 = s * 32;
#pragma unroll
        for (int p = 0; p < 4; ++p) {
            int row = lr + p * 32;
            cp_async16(&Ad[row * 36 + lc], &A[(bm + row) * 256 + k0 + lc]);
            cp_async16(&Wd[row * 36 + lc], &W[(long)(bn + row) * 256 + k0 + lc]);
        }
        asm volatile("cp.async.commit_group;" ::: "memory");
    }

#pragma unroll
    for (int it = 0; it < 8; ++it) {
        if (it < 7)
            asm volatile("cp.async.wait_group 1;" ::: "memory");
        else
            asm volatile("cp.async.wait_group 0;" ::: "memory");
        __syncthreads();

        if (it + 2 < 8) {
            const int s = (it + 2) % 3;
            float* Ad = smem + s * STAGE_F;
            float* Wd = Ad + TILE_F;
            const int k0 = (it + 2) * 32;
#pragma unroll
            for (int p = 0; p < 4; ++p) {
                int row = lr + p * 32;
                cp_async16(&Ad[row * 36 + lc], &A[(bm + row) * 256 + k0 + lc]);
                cp_async16(&Wd[row * 36 + lc], &W[(long)(bn + row) * 256 + k0 + lc]);
            }
            asm volatile("cp.async.commit_group;" ::: "memory");
        }

        const float* Ab = smem + (it % 3) * STAGE_F;
        const float* Wb = Ab + TILE_F;
#pragma unroll
        for (int ks = 0; ks < 4; ++ks) {
            const int kk = ks * 8;
            uint32_t af[4][4];
            uint32_t bf[4][2];
#pragma unroll
            for (int mt = 0; mt < 4; ++mt) {
                const int m0 = wm + mt * 16 + gid;
                af[mt][0] = __float_as_uint(Ab[m0 * 36 + kk + tig]);
                af[mt][1] = __float_as_uint(Ab[(m0 + 8) * 36 + kk + tig]);
                af[mt][2] = __float_as_uint(Ab[m0 * 36 + kk + tig + 4]);
                af[mt][3] = __float_as_uint(Ab[(m0 + 8) * 36 + kk + tig + 4]);
            }
#pragma unroll
            for (int nt = 0; nt < 4; ++nt) {
                const int n0 = wn + nt * 8 + gid;
                bf[nt][0] = __float_as_uint(Wb[n0 * 36 + kk + tig]);
                bf[nt][1] = __float_as_uint(Wb[n0 * 36 + kk + tig + 4]);
            }
#pragma unroll
            for (int mt = 0; mt < 4; ++mt)
#pragma unroll
                for (int nt = 0; nt < 4; ++nt)
                    MMA_TF32(acc[mt][nt], af[mt], bf[nt]);
        }
    }

    // epilogue
    const bool selfRows = (bm >= E1);
#pragma unroll
    for (int mt = 0; mt < 4; ++mt) {
#pragma unroll
        for (int nt = 0; nt < 4; ++nt) {
            const int col = bn + wn + nt * 8 + 2 * tig;
            const float bv0 = bias[col];
            const float bv1 = bias[col + 1];
            float a0 = fmaxf(acc[mt][nt][0] + bv0, 0.f);
            float a1 = fmaxf(acc[mt][nt][1] + bv1, 0.f);
            float a2 = fmaxf(acc[mt][nt][2] + bv0, 0.f);
            float a3 = fmaxf(acc[mt][nt][3] + bv1, 0.f);
            if (selfRows) {
                const long r0 = bm + wm + mt * 16 + gid - E1;
                float2 v0 = {a0, a1}, v1 = {a2, a3};
                *(float2*)&Cself[r0 * 256 + col] = v0;
                *(float2*)&Cself[(r0 + 8) * 256 + col] = v1;
            } else {
                // segment = 16 consecutive rows = this warp's mt-th row group
                float s0 = a0 + a2;
                float s1 = a1 + a3;
                s0 += __shfl_xor_sync(0xffffffffu, s0, 4);
                s1 += __shfl_xor_sync(0xffffffffu, s1, 4);
                s0 += __shfl_xor_sync(0xffffffffu, s0, 8);
                s1 += __shfl_xor_sync(0xffffffffu, s1, 8);
                s0 += __shfl_xor_sync(0xffffffffu, s0, 16);
                s1 += __shfl_xor_sync(0xffffffffu, s1, 16);
                if (gid == 0) {
                    const long seg = ((bm + wm) >> 4) + mt;
                    float2 v = {s0, s1};
                    *(float2*)&Agg[seg * 256 + col] = v;
                }
            }
        }
    }
}

// ---------------------------------------------------------------------------
// Kernel 3: gemm2 — Bcat tile from [agg1 | h1s*decay], tf32 MMA vs W2.
// NEW: K-chunk 64 (8 chunks instead of 16) -> half the barrier/wait rounds,
// 2x MMA work per round. Ws stride 68 keeps B-fragment LDS conflict-free.
// smem: As 16*516 + 3 * 128*68 floats = 137 KB.
// ---------------------------------------------------------------------------
#define AS2_STRIDE 516
#define AS2_F      (16 * AS2_STRIDE)   // 8256 floats
#define WS2_STRIDE 68
#define WS2_F      (128 * WS2_STRIDE)  // 8704 floats per stage

__global__ __launch_bounds__(256) void gemm2_fused(const float* __restrict__ ts,
                                                   const float* __restrict__ n_times1,
                                                   const float* __restrict__ t_kernel,
                                                   float* __restrict__ out) {
    extern __shared__ float sm2[];      // As[16][516] | Ws[3][128][68]
    float* As = sm2;
    float* Ws = sm2 + AS2_F;

    const int bm   = blockIdx.x * 16;
    const int tid  = threadIdx.x;
    const int lane = tid & 31;
    const int warp = tid >> 5;          // 0..7
    const int gid  = lane >> 2;         // 0..7
    const int tig  = lane & 3;          // 0..3
    const float tk = t_kernel[0];

    // ---- Phase A: As[16][512] = [agg1 row | h1s row * decay], coalesced ----
#pragma unroll
    for (int p = 0; p < 8; ++p) {
        int idx = tid + p * 256;        // 0..2047
        int r = idx >> 7;               // 0..15
        int c = idx & 127;              // float4 col 0..127
        int b = bm + r;
        float4 v;
        if (c < 64) {
            v = ((const float4*)(g_agg1 + (long)b * 256))[c];
        } else {
            float dec = __expf(-tk * (ts[b] - n_times1[b]));
            float4 t = ((const float4*)(g_h1s + (long)b * 256))[c - 64];
            v.x = t.x * dec; v.y = t.y * dec; v.z = t.z * dec; v.w = t.w * dec;
        }
        float4 o = { to_tf32(v.x), to_tf32(v.y), to_tf32(v.z), to_tf32(v.w) };
        *(float4*)&As[r * AS2_STRIDE + c * 4] = o;
    }

    // ---- prologue: stage W2 chunks 0,1 (K-chunk = 64) ----
    // per stage: 128 rows x 16 float4 = 2048 float4 / 256 thr = 8 per thread
#pragma unroll
    for (int s = 0; s < 2; ++s) {
        float* Wd = Ws + s * WS2_F;
        const int k0 = s * 64;
#pragma unroll
        for (int p = 0; p < 8; ++p) {
            int idx = tid + p * 256;    // 0..2047
            int n = idx >> 4;           // 0..127
            int k4 = (idx & 15) << 2;   // 0,4,...,60
            cp_async16(&Wd[n * WS2_STRIDE + k4], &g_W2[(long)n * 512 + k0 + k4]);
        }
        asm volatile("cp.async.commit_group;" ::: "memory");
    }

    float acc[2][4];
#pragma unroll
    for (int nt = 0; nt < 2; ++nt)
#pragma unroll
        for (int q = 0; q < 4; ++q) acc[nt][q] = 0.f;

    // ---- mainloop: 8 chunks of K=64 ----
#pragma unroll
    for (int ch = 0; ch < 8; ++ch) {
        if (ch < 7)
            asm volatile("cp.async.wait_group 1;" ::: "memory");
        else
            asm volatile("cp.async.wait_group 0;" ::: "memory");
        __syncthreads();   // also orders Phase-A As writes before first reads

        if (ch + 2 < 8) {
            float* Wd = Ws + ((ch + 2) % 3) * WS2_F;
            const int k0 = (ch + 2) * 64;
#pragma unroll
            for (int p = 0; p < 8; ++p) {
                int idx = tid + p * 256;
                int n = idx >> 4;
                int k4 = (idx & 15) << 2;
                cp_async16(&Wd[n * WS2_STRIDE + k4], &g_W2[(long)n * 512 + k0 + k4]);
            }
            asm volatile("cp.async.commit_group;" ::: "memory");
        }

        const float* Wb = Ws + (ch % 3) * WS2_F;
#pragma unroll
        for (int ks = 0; ks < 8; ++ks) {
            const int ka = ch * 64 + ks * 8;   // global k into As
            const int kw = ks * 8;             // local k into Wb
            uint32_t af[4];
            af[0] = __float_as_uint(As[gid * AS2_STRIDE + ka + tig]);
            af[1] = __float_as_uint(As[(gid + 8) * AS2_STRIDE + ka + tig]);
            af[2] = __float_as_uint(As[gid * AS2_STRIDE + ka + tig + 4]);
            af[3] = __float_as_uint(As[(gid + 8) * AS2_STRIDE + ka + tig + 4]);
#pragma unroll
            for (int nt = 0; nt < 2; ++nt) {
                const int n0 = warp * 16 + nt * 8 + gid;
                uint32_t bf[2];
                bf[0] = __float_as_uint(Wb[n0 * WS2_STRIDE + kw + tig]);
                bf[1] = __float_as_uint(Wb[n0 * WS2_STRIDE + kw + tig + 4]);
                MMA_TF32(acc[nt], af, bf);
            }
        }
    }

    // ---- epilogue: bias + relu ----
#pragma unroll
    for (int nt = 0; nt < 2; ++nt) {
        const int col = warp * 16 + nt * 8 + 2 * tig;
        const float bv0 = g_b2[col];
        const float bv1 = g_b2[col + 1];
        float2 v0, v1;
        v0.x = acc[nt][0] + bv0; v0.x = v0.x > 0.f ? v0.x : 0.f;
        v0.y = acc[nt][1] + bv1; v0.y = v0.y > 0.f ? v0.y : 0.f;
        v1.x = acc[nt][2] + bv0; v1.x = v1.x > 0.f ? v1.x : 0.f;
        v1.y = acc[nt][3] + bv1; v1.y = v1.y > 0.f ? v1.y : 0.f;
        *(float2*)&out[(long)(bm + gid) * OUTD + col] = v0;
        *(float2*)&out[(long)(bm + gid + 8) * OUTD + col] = v1;
    }
}

// ---------------------------------------------------------------------------
// Launch
// ---------------------------------------------------------------------------
extern "C" void kernel_launch(void* const* d_in, const int* in_sizes, int n_in,
                              void* d_out, int out_size) {
    const float* x        = (const float*)d_in[0];
    const float* ts       = (const float*)d_in[1];
    const float* t2       = (const float*)d_in[2];
    const float* n_times1 = (const float*)d_in[3];
    const float* n_times2 = (const float*)d_in[4];
    const float* W1n      = (const float*)d_in[5];
    const float* b1n      = (const float*)d_in[6];
    const float* W1h      = (const float*)d_in[7];
    const float* b1h      = (const float*)d_in[8];
    const float* W2n      = (const float*)d_in[9];
    const float* b2n      = (const float*)d_in[10];
    const float* W2h      = (const float*)d_in[11];
    const float* b2h      = (const float*)d_in[12];
    const float* t_kernel = (const float*)d_in[13];
    const int*   nodes2   = (const int*)d_in[14];
    const int*   nbr2     = (const int*)d_in[15];
    float* out = (float*)d_out;

    float *pAcat, *pW1, *pb1, *pH1s, *pAgg;
    cudaGetSymbolAddress((void**)&pAcat, g_Acat);
    cudaGetSymbolAddress((void**)&pW1, g_W1);
    cudaGetSymbolAddress((void**)&pb1, g_b1);
    cudaGetSymbolAddress((void**)&pH1s, g_h1s);
    cudaGetSymbolAddress((void**)&pAgg, g_agg1);

    const int smem1 = 3 * STAGE_F * sizeof(float);                 // 110592 B
    cudaFuncSetAttribute(gemm1_tf32, cudaFuncAttributeMaxDynamicSharedMemorySize, smem1);
    const int smem2 = (AS2_F + 3 * WS2_F) * sizeof(float);         // 137472 B
    cudaFuncSetAttribute(gemm2_fused, cudaFuncAttributeMaxDynamicSharedMemorySize, smem2);

    build_acat<<<N2 / 8, 256>>>(x, nodes2, nbr2, t2, n_times2, t_kernel,
                                W1n, b1n, W1h, b1h, W2n, b2n, W2h, b2h);

    dim3 g1(2, N2 / 128);   // (2, 272)
    gemm1_tf32<<<g1, 256, smem1>>>(pAcat, pW1, pb1, pH1s, pAgg);

    gemm2_fused<<<BATCH / 16, 256, smem2>>>(ts, n_times1, t_kernel, out);
}